// round 1
// baseline (speedup 1.0000x reference)
#include <cuda_runtime.h>
#include <cstdint>

#define B_  2048
#define T_  336
#define F_  10
#define H1_ 70
#define H2_ 21
#define D1_ 30
#define D2_ 20

// ---------------- scratch (__device__ globals; no allocations) ----------------
__device__ float g_xT[(size_t)T_ * B_ * F_];          // x transposed to [T][B][F]
__device__ float g_h1[(size_t)T_ * B_ * 2 * H1_];     // layer1 output [T][B][140]
__device__ float g_h2[(size_t)T_ * B_ * 2 * H2_];     // layer2 output [T][B][42]

// ---------------- activations (accurate fast-math, ~1e-6 rel) ----------------
__device__ __forceinline__ float fsigm(float x) {
    return __fdividef(1.f, 1.f + __expf(-x));
}
__device__ __forceinline__ float ftanh_(float x) {
    // tanh(x) = 1 - 2/(1+e^{2x}); saturates correctly for |x| large (no NaN)
    return 1.f - 2.f * __fdividef(1.f, 1.f + __expf(2.f * x));
}

// ---------------- transpose x: [B][T][F] -> [T][B][F] ----------------
__global__ void transpose_x(const float* __restrict__ x) {
    int gid = blockIdx.x * blockDim.x + threadIdx.x;
    if (gid < B_ * T_ * F_) {
        int f = gid % F_;
        int t = (gid / F_) % T_;
        int b = gid / (F_ * T_);
        g_xT[((size_t)t * B_ + b) * F_ + f] = x[gid];
    }
}

// ---------------- persistent bidirectional LSTM layer ----------------
// One block = one batch chunk of BB samples, one direction (blockIdx.y).
// Weights (k-major), h, c live in smem for the whole T loop.
// g[b][j] = bias[j] + sum_k a[b][k] * W[k][j],  a = [x_t | h_{t-1}], K = I+H.
template <int I, int H, int BB, int TB>
__global__ void lstm_kernel(const float* __restrict__ xin, int xin_pitch,
                            const float* __restrict__ Wih_f, const float* __restrict__ Whh_f,
                            const float* __restrict__ bih_f, const float* __restrict__ bhh_f,
                            const float* __restrict__ Wih_b, const float* __restrict__ Whh_b,
                            const float* __restrict__ bih_b, const float* __restrict__ bhh_b,
                            float* __restrict__ hout, int hout_pitch)
{
    constexpr int G   = 4 * H;       // gate width
    constexpr int K   = I + H;       // reduction length
    constexpr int KP  = K + 1;       // padded row pitch for a_s
    constexpr int NJC = G / 4;       // float4 column chunks
    constexpr int NSG = BB / TB;     // sample groups
    constexpr int NW  = NSG * NJC;   // active matvec workers

    extern __shared__ float smem[];
    float* sW  = smem;                                   // [K][G]   k-major
    float* gS  = sW + ((K * G + 3) / 4) * 4;             // [BB][G]  gate pre-activations
    float* aS  = gS + BB * G;                            // [BB][KP] concat(x, h)
    float* cS  = aS + ((BB * KP + 3) / 4) * 4;           // [BB][H]
    float* sb  = cS + BB * H;                            // [G]

    const int  dir  = blockIdx.y;
    const float* Wih = dir ? Wih_b : Wih_f;
    const float* Whh = dir ? Whh_b : Whh_f;
    const float* bih = dir ? bih_b : bih_f;
    const float* bhh = dir ? bhh_b : bhh_f;
    const int  b0   = blockIdx.x * BB;
    const int  hoff = dir * H;
    const int  tid  = threadIdx.x;
    const int  nthr = blockDim.x;

    // ---- load weights transposed to k-major (one-time) ----
    for (int idx = tid; idx < I * G; idx += nthr) {
        int k = idx / G, j = idx % G;
        sW[idx] = Wih[j * I + k];
    }
    for (int idx = tid; idx < H * G; idx += nthr) {
        int k = idx / G, j = idx % G;
        sW[(I + k) * G + j] = Whh[j * H + k];
    }
    for (int j = tid; j < G; j += nthr) sb[j] = bih[j] + bhh[j];
    for (int idx = tid; idx < BB * H; idx += nthr) {
        cS[idx] = 0.f;
        int b = idx / H, h = idx % H;
        aS[b * KP + I + h] = 0.f;
    }
    __syncthreads();

    const int  sg = tid / NJC;
    const int  jc = tid % NJC;
    const bool active = (tid < NW);

    for (int s = 0; s < T_; ++s) {
        const int t = dir ? (T_ - 1 - s) : s;

        // ---- stage x_t for this chunk (coalesced) ----
        const float* xrow = xin + ((size_t)t * B_ + b0) * xin_pitch;
        for (int idx = tid; idx < BB * I; idx += nthr) {
            int b = idx / I, k = idx % I;
            aS[b * KP + k] = xrow[b * xin_pitch + k];
        }
        __syncthreads();

        // ---- matvec: g = bias + [x|h] @ W ----
        if (active) {
            float4 bias4 = reinterpret_cast<const float4*>(sb)[jc];
            float4 acc[TB];
            #pragma unroll
            for (int r = 0; r < TB; ++r) acc[r] = bias4;

            const float4* sW4  = reinterpret_cast<const float4*>(sW);
            const float*  arow = aS + (sg * TB) * KP;
            #pragma unroll 4
            for (int k = 0; k < K; ++k) {
                float4 w = sW4[k * NJC + jc];
                #pragma unroll
                for (int r = 0; r < TB; ++r) {
                    float av = arow[r * KP + k];   // warp-broadcast
                    acc[r].x = fmaf(av, w.x, acc[r].x);
                    acc[r].y = fmaf(av, w.y, acc[r].y);
                    acc[r].z = fmaf(av, w.z, acc[r].z);
                    acc[r].w = fmaf(av, w.w, acc[r].w);
                }
            }
            float4* gS4 = reinterpret_cast<float4*>(gS);
            #pragma unroll
            for (int r = 0; r < TB; ++r) gS4[(sg * TB + r) * NJC + jc] = acc[r];
        }
        __syncthreads();

        // ---- gates + state update + output store ----
        float* orow = hout + ((size_t)t * B_ + b0) * hout_pitch + hoff;
        for (int idx = tid; idx < BB * H; idx += nthr) {
            int b = idx / H, h = idx % H;
            const float* grow = gS + b * G;
            float gi = grow[h];
            float gf = grow[H + h];
            float gg = grow[2 * H + h];
            float go = grow[3 * H + h];
            float c  = fsigm(gf) * cS[idx] + fsigm(gi) * ftanh_(gg);
            cS[idx]  = c;
            float hn = fsigm(go) * ftanh_(c);
            aS[b * KP + I + h] = hn;
            orow[b * hout_pitch + h] = hn;
        }
        __syncthreads();
    }
}

// ---------------- fused dense head: relu(relu(h@wd1^T+b)@wd2^T+b)@wo^T+bo ----------------
__global__ void dense_kernel(const float* __restrict__ wd1, const float* __restrict__ bd1,
                             const float* __restrict__ wd2, const float* __restrict__ bd2,
                             const float* __restrict__ wo,  const float* __restrict__ bo,
                             float* __restrict__ out)
{
    constexpr int IN = 2 * H2_;  // 42
    __shared__ float s1[D1_ * IN], sb1[D1_], s2[D2_ * D1_], sb2[D2_], sWo[D2_], sBo;
    int tid = threadIdx.x;
    for (int i = tid; i < D1_ * IN; i += blockDim.x) s1[i] = wd1[i];
    for (int i = tid; i < D2_ * D1_; i += blockDim.x) s2[i] = wd2[i];
    if (tid < D1_) sb1[tid] = bd1[tid];
    if (tid < D2_) { sb2[tid] = bd2[tid]; sWo[tid] = wo[tid]; }
    if (tid == 0) sBo = bo[0];
    __syncthreads();

    int gid = blockIdx.x * blockDim.x + tid;   // row = t*B + b
    if (gid >= T_ * B_) return;

    float in[IN];
    const float* hrow = g_h2 + (size_t)gid * IN;
    #pragma unroll
    for (int k = 0; k < IN; ++k) in[k] = hrow[k];

    float acc2[D2_];
    #pragma unroll
    for (int k = 0; k < D2_; ++k) acc2[k] = sb2[k];

    #pragma unroll 2
    for (int j = 0; j < D1_; ++j) {
        float v = sb1[j];
        #pragma unroll
        for (int k = 0; k < IN; ++k) v = fmaf(in[k], s1[j * IN + k], v);
        v = fmaxf(v, 0.f);
        #pragma unroll
        for (int k = 0; k < D2_; ++k) acc2[k] = fmaf(v, s2[k * D1_ + j], acc2[k]);
    }
    float y = sBo;
    #pragma unroll
    for (int k = 0; k < D2_; ++k) y = fmaf(fmaxf(acc2[k], 0.f), sWo[k], y);

    int b = gid % B_, t = gid / B_;
    out[(size_t)b * T_ + t] = y;   // output [B][T][1]
}

// ---------------- host glue ----------------
static constexpr size_t lstm_smem_bytes(int I, int H, int BB) {
    int G = 4 * H, K = I + H, KP = K + 1;
    size_t f = (size_t)((K * G + 3) / 4) * 4 + (size_t)BB * G +
               (size_t)((BB * KP + 3) / 4) * 4 + (size_t)BB * H + (size_t)G;
    return f * sizeof(float);
}

extern "C" void kernel_launch(void* const* d_in, const int* in_sizes, int n_in,
                              void* d_out, int out_size)
{
    const float* x      = (const float*)d_in[0];
    const float* w1f_ih = (const float*)d_in[1];
    const float* w1f_hh = (const float*)d_in[2];
    const float* b1f_ih = (const float*)d_in[3];
    const float* b1f_hh = (const float*)d_in[4];
    const float* w1b_ih = (const float*)d_in[5];
    const float* w1b_hh = (const float*)d_in[6];
    const float* b1b_ih = (const float*)d_in[7];
    const float* b1b_hh = (const float*)d_in[8];
    const float* w2f_ih = (const float*)d_in[9];
    const float* w2f_hh = (const float*)d_in[10];
    const float* b2f_ih = (const float*)d_in[11];
    const float* b2f_hh = (const float*)d_in[12];
    const float* w2b_ih = (const float*)d_in[13];
    const float* w2b_hh = (const float*)d_in[14];
    const float* b2b_ih = (const float*)d_in[15];
    const float* b2b_hh = (const float*)d_in[16];
    const float* wd1    = (const float*)d_in[17];
    const float* bd1    = (const float*)d_in[18];
    const float* wd2    = (const float*)d_in[19];
    const float* bd2    = (const float*)d_in[20];
    const float* wo     = (const float*)d_in[21];
    const float* bo     = (const float*)d_in[22];
    float* out = (float*)d_out;

    void *pxT, *ph1, *ph2;
    cudaGetSymbolAddress(&pxT, g_xT);
    cudaGetSymbolAddress(&ph1, g_h1);
    cudaGetSymbolAddress(&ph2, g_h2);
    float* xT = (float*)pxT;
    float* h1 = (float*)ph1;
    float* h2 = (float*)ph2;

    const size_t smem1 = lstm_smem_bytes(F_, H1_, 32);        // ~146 KB
    const size_t smem2 = lstm_smem_bytes(2 * H1_, H2_, 32);   // ~89 KB
    cudaFuncSetAttribute(lstm_kernel<F_, H1_, 32, 8>,
                         cudaFuncAttributeMaxDynamicSharedMemorySize, (int)smem1);
    cudaFuncSetAttribute(lstm_kernel<2 * H1_, H2_, 32, 4>,
                         cudaFuncAttributeMaxDynamicSharedMemorySize, (int)smem2);

    // 1) transpose x to [T][B][F]
    transpose_x<<<(B_ * T_ * F_ + 255) / 256, 256>>>(x);

    // 2) layer 1 (both directions in parallel): 64 chunks x 2 dirs = 128 blocks
    lstm_kernel<F_, H1_, 32, 8><<<dim3(B_ / 32, 2), 288, smem1>>>(
        xT, F_,
        w1f_ih, w1f_hh, b1f_ih, b1f_hh,
        w1b_ih, w1b_hh, b1b_ih, b1b_hh,
        h1, 2 * H1_);

    // 3) layer 2
    lstm_kernel<2 * H1_, H2_, 32, 4><<<dim3(B_ / 32, 2), 192, smem2>>>(
        h1, 2 * H1_,
        w2f_ih, w2f_hh, b2f_ih, b2f_hh,
        w2b_ih, w2b_hh, b2b_ih, b2b_hh,
        h2, 2 * H2_);

    // 4) dense head
    dense_kernel<<<(T_ * B_ + 255) / 256, 256>>>(wd1, bd1, wd2, bd2, wo, bo, out);
}

// round 2
// speedup vs baseline: 1.4840x; 1.4840x over previous
#include <cuda_runtime.h>
#include <cstdint>

#define B_  2048
#define T_  336
#define F_  10
#define H1_ 70
#define H2_ 21
#define D1_ 30
#define D2_ 20

// ---------------- scratch (__device__ globals; no allocations) ----------------
__device__ float g_xT [(size_t)T_ * B_ * F_];          // x transposed [T][B][10]
__device__ float g_h1 [(size_t)T_ * B_ * (2*H1_)];     // layer1 out   [T][B][140]
__device__ float g_xg2[(size_t)T_ * B_ * (8*H2_)];     // layer2 input gates [T][B][168]
__device__ float g_h2 [(size_t)T_ * B_ * (2*H2_)];     // layer2 out   [T][B][42]
__device__ float g_w2t[140 * 168];                     // W2_ih^T packed, both dirs
__device__ float g_b2 [168];

// ---------------- packed f32x2 helpers ----------------
__device__ __forceinline__ unsigned long long pk2(float lo, float hi) {
    unsigned long long r;
    asm("mov.b64 %0, {%1, %2};" : "=l"(r) : "f"(lo), "f"(hi));
    return r;
}
__device__ __forceinline__ unsigned long long fma2_(unsigned long long a,
                                                    unsigned long long b,
                                                    unsigned long long c) {
    unsigned long long d;
    asm("fma.rn.f32x2 %0, %1, %2, %3;" : "=l"(d) : "l"(a), "l"(b), "l"(c));
    return d;
}

// ---------------- activations (accurate fast-math, ~1e-6 rel) ----------------
__device__ __forceinline__ float fsigm(float x) {
    return __fdividef(1.f, 1.f + __expf(-x));
}
__device__ __forceinline__ float ftanh_(float x) {
    return 1.f - 2.f * __fdividef(1.f, 1.f + __expf(2.f * x));
}

// ---------------- transpose x: [B][T][F] -> [T][B][F] ----------------
__global__ void transpose_x(const float* __restrict__ x) {
    int gid = blockIdx.x * blockDim.x + threadIdx.x;
    if (gid < B_ * T_ * F_) {
        int f = gid % F_;
        int t = (gid / F_) % T_;
        int b = gid / (F_ * T_);
        g_xT[((size_t)t * B_ + b) * F_ + f] = x[gid];
    }
}

// ---------------- prep: transpose layer-2 input weights to k-major ----------------
__global__ void prep_w2(const float* __restrict__ wf, const float* __restrict__ wb,
                        const float* __restrict__ bfi, const float* __restrict__ bfh,
                        const float* __restrict__ bbi, const float* __restrict__ bbh) {
    int i = blockIdx.x * blockDim.x + threadIdx.x;
    if (i < 168 * 140) {
        int jj = i / 140;
        int k  = i % 140;
        int dir = jj / 84, j = jj % 84;
        const float* w = dir ? wb : wf;
        g_w2t[k * 168 + jj] = w[j * 140 + k];
    }
    if (i < 168) {
        int dir = i / 84, j = i % 84;
        g_b2[i] = dir ? (bbi[j] + bbh[j]) : (bfi[j] + bfh[j]);
    }
}

// ================= layer 1: fused-input recurrent LSTM =================
// block = 32 samples x 1 direction; K = 10(x) + 70(h) = 80; G padded 280->288
__global__ __launch_bounds__(288, 1)
void lstm1_kernel(const float* __restrict__ Wih_f, const float* __restrict__ Whh_f,
                  const float* __restrict__ bih_f, const float* __restrict__ bhh_f,
                  const float* __restrict__ Wih_b, const float* __restrict__ Whh_b,
                  const float* __restrict__ bih_b, const float* __restrict__ bhh_b)
{
    constexpr int I = 10, H = 70, K = 80, KP = 84, G = 280, GP = 288, NJC = 72, TB = 8;
    extern __shared__ float sm[];
    float* sW = sm;               // [80][288] k-major, packed pairs
    float* gS = sW + K * GP;      // [32][288]
    float* aS = gS + 32 * GP;     // [32][84]  (x | h | pad)
    float* cS = aS + 32 * KP;     // [32][70]
    float* sb = cS + 32 * H;      // [288]

    const int dir = blockIdx.y;
    const float* Wih = dir ? Wih_b : Wih_f;
    const float* Whh = dir ? Whh_b : Whh_f;
    const float* bih = dir ? bih_b : bih_f;
    const float* bhh = dir ? bhh_b : bhh_f;
    const int b0  = blockIdx.x * 32;
    const int tid = threadIdx.x;

    for (int idx = tid; idx < K * GP; idx += 288) {
        int k = idx / GP, j = idx % GP;
        float v = 0.f;
        if (j < G) v = (k < I) ? Wih[j * I + k] : Whh[j * H + (k - I)];
        sW[idx] = v;
    }
    for (int j = tid; j < GP; j += 288) sb[j] = (j < G) ? (bih[j] + bhh[j]) : 0.f;
    for (int idx = tid; idx < 32 * KP; idx += 288) aS[idx] = 0.f;
    for (int idx = tid; idx < 32 * H; idx += 288) cS[idx] = 0.f;

    // x prefetch mapping (320 floats = 80 float4, tid<80)
    const bool xp = tid < 80;
    int xb[4] = {0,0,0,0}, xk[4] = {0,0,0,0};
    if (xp) {
        #pragma unroll
        for (int c = 0; c < 4; ++c) { int i = tid * 4 + c; xb[c] = i / I; xk[c] = i % I; }
    }
    // activation mapping (precomputed, constant across steps)
    int nact = 0, actB[8], actH[8];
    for (int idx = tid; idx < 32 * H; idx += 288) {
        actB[nact] = idx / H; actH[nact] = idx % H; ++nact;
    }

    const int sg = tid / NJC, jc = tid % NJC;
    const float* arow = aS + sg * TB * KP;

    int t = dir ? (T_ - 1) : 0;
    const int tstep = dir ? -1 : 1;
    float4 xpre = make_float4(0.f, 0.f, 0.f, 0.f);
    if (xp) xpre = ((const float4*)(g_xT + ((size_t)t * B_ + b0) * I))[tid];
    __syncthreads();

    for (int s = 0; s < T_; ++s, t += tstep) {
        if (xp) {
            aS[xb[0] * KP + xk[0]] = xpre.x;
            aS[xb[1] * KP + xk[1]] = xpre.y;
            aS[xb[2] * KP + xk[2]] = xpre.z;
            aS[xb[3] * KP + xk[3]] = xpre.w;
        }
        __syncthreads();
        if (xp && s + 1 < T_)
            xpre = ((const float4*)(g_xT + ((size_t)(t + tstep) * B_ + b0) * I))[tid];

        // ---- packed matvec: g = bias + [x|h] @ W ----
        {
            float4 b4 = ((const float4*)sb)[jc];
            ulonglong2 binit = *reinterpret_cast<ulonglong2*>(&b4);
            ulonglong2 acc[TB];
            #pragma unroll
            for (int r = 0; r < TB; ++r) acc[r] = binit;
            const ulonglong2* sWp = (const ulonglong2*)sW;
            #pragma unroll 2
            for (int kk = 0; kk < K; kk += 4) {
                float4 a4[TB];
                #pragma unroll
                for (int r = 0; r < TB; ++r)
                    a4[r] = *(const float4*)(arow + r * KP + kk);
                #pragma unroll
                for (int u = 0; u < 4; ++u) {
                    ulonglong2 w = sWp[(kk + u) * NJC + jc];
                    #pragma unroll
                    for (int r = 0; r < TB; ++r) {
                        float a = reinterpret_cast<const float*>(&a4[r])[u];
                        unsigned long long ad = pk2(a, a);
                        acc[r].x = fma2_(ad, w.x, acc[r].x);
                        acc[r].y = fma2_(ad, w.y, acc[r].y);
                    }
                }
            }
            ulonglong2* gSp = (ulonglong2*)gS;
            #pragma unroll
            for (int r = 0; r < TB; ++r) gSp[(sg * TB + r) * NJC + jc] = acc[r];
        }
        __syncthreads();

        // ---- gates + state update + h store ----
        float* orow = g_h1 + ((size_t)t * B_ + b0) * (2 * H1_) + dir * H;
        for (int i = 0; i < nact; ++i) {
            int b = actB[i], h = actH[i], idx = b * H + h;
            const float* grow = gS + b * GP;
            float c = fsigm(grow[H + h]) * cS[idx] + fsigm(grow[h]) * ftanh_(grow[2 * H + h]);
            cS[idx] = c;
            float hn = fsigm(grow[3 * H + h]) * ftanh_(c);
            aS[b * KP + I + h] = hn;
            orow[b * (2 * H1_) + h] = hn;
        }
    }
}

// ================= layer-2 input GEMM: xg2 = h1 @ W2ih^T + biases =================
// block = 64 rows; K=140, G=168 (fwd 0..83 | bwd 84..167)
__global__ __launch_bounds__(352, 1)
void xg2_kernel()
{
    constexpr int BB = 64, K = 140, KP = 144, G = 168, NJC = 42, TB = 8;
    extern __shared__ float sm[];
    float* sW = sm;               // [140][168]
    float* aS = sW + K * G;       // [64][144]
    float* sb = aS + BB * KP;     // [168]
    const int tid = threadIdx.x;
    const size_t row0 = (size_t)blockIdx.x * BB;

    {
        const float4* wsrc = (const float4*)g_w2t;
        float4* wdst = (float4*)sW;
        for (int i = tid; i < K * G / 4; i += 352) wdst[i] = wsrc[i];
    }
    for (int j = tid; j < G; j += 352) sb[j] = g_b2[j];
    {
        const float4* src = (const float4*)(g_h1 + row0 * K);
        float4* dst = (float4*)aS;
        for (int i = tid; i < BB * K / 4; i += 352) {
            int r = i / 35, c = i % 35;          // 35 float4 per 140-float row
            dst[r * 36 + c] = src[i];            // aS pitch = 144 floats = 36 float4
        }
    }
    __syncthreads();

    if (tid < 336) {
        const int sg = tid / NJC, jc = tid % NJC;
        const float* arow = aS + sg * TB * KP;
        float4 b4 = ((const float4*)sb)[jc];
        ulonglong2 binit = *reinterpret_cast<ulonglong2*>(&b4);
        ulonglong2 acc[TB];
        #pragma unroll
        for (int r = 0; r < TB; ++r) acc[r] = binit;
        const ulonglong2* sWp = (const ulonglong2*)sW;
        #pragma unroll 2
        for (int kk = 0; kk < K; kk += 4) {
            float4 a4[TB];
            #pragma unroll
            for (int r = 0; r < TB; ++r)
                a4[r] = *(const float4*)(arow + r * KP + kk);
            #pragma unroll
            for (int u = 0; u < 4; ++u) {
                ulonglong2 w = sWp[(kk + u) * NJC + jc];
                #pragma unroll
                for (int r = 0; r < TB; ++r) {
                    float a = reinterpret_cast<const float*>(&a4[r])[u];
                    unsigned long long ad = pk2(a, a);
                    acc[r].x = fma2_(ad, w.x, acc[r].x);
                    acc[r].y = fma2_(ad, w.y, acc[r].y);
                }
            }
        }
        float4* outp = (float4*)(g_xg2 + row0 * G);
        #pragma unroll
        for (int r = 0; r < TB; ++r)
            outp[(sg * TB + r) * NJC + jc] = *reinterpret_cast<float4*>(&acc[r]);
    }
}

// ================= layer 2: recurrent-only LSTM (K = 21) =================
__global__ __launch_bounds__(256, 1)
void lstm2_kernel(const float* __restrict__ Whh_f, const float* __restrict__ Whh_b)
{
    constexpr int H = 21, K4 = 24, KP = 28, G = 84, GP = 96, NJC = 24, TB = 4;
    extern __shared__ float sm[];
    float* sW = sm;                // [24][96]
    float* gS = sW + K4 * GP;      // [2][32][96] double-buffered
    float* aS = gS + 2 * 32 * GP;  // [32][28]
    float* cS = aS + 32 * KP;      // [32][21]

    const int dir = blockIdx.y;
    const float* Whh = dir ? Whh_b : Whh_f;
    const int b0  = blockIdx.x * 32;
    const int tid = threadIdx.x;

    for (int idx = tid; idx < K4 * GP; idx += 256) {
        int k = idx / GP, j = idx % GP;
        sW[idx] = (k < H && j < G) ? Whh[j * H + k] : 0.f;
    }
    for (int idx = tid; idx < 32 * KP; idx += 256) aS[idx] = 0.f;
    for (int idx = tid; idx < 32 * H; idx += 256) cS[idx] = 0.f;

    // g prefetch mapping: 672 float4, tid<168 loads 4 each
    const bool gp = tid < 168;
    int gb[4] = {0,0,0,0}, gc[4] = {0,0,0,0};
    if (gp) {
        #pragma unroll
        for (int q = 0; q < 4; ++q) { int i = tid * 4 + q; gb[q] = i / 21; gc[q] = i % 21; }
    }
    int nact = 0, actB[3], actH[3];
    for (int idx = tid; idx < 32 * H; idx += 256) {
        actB[nact] = idx / H; actH[nact] = idx % H; ++nact;
    }
    const int sg = tid / NJC, jc = tid % NJC;
    const float* arow = aS + sg * TB * KP;

    int t = dir ? (T_ - 1) : 0;
    const int tstep = dir ? -1 : 1;
    float4 gpre[4];
    if (gp) {
        const float4* src = (const float4*)(g_xg2 + ((size_t)t * B_ + b0) * 168 + dir * 84);
        #pragma unroll
        for (int q = 0; q < 4; ++q) gpre[q] = src[gb[q] * 42 + gc[q]];
    }
    __syncthreads();

    for (int s = 0; s < T_; ++s, t += tstep) {
        const int p = s & 1;
        float4* gSd = (float4*)(gS + p * 32 * GP);
        if (gp) {
            #pragma unroll
            for (int q = 0; q < 4; ++q) gSd[gb[q] * 24 + gc[q]] = gpre[q];
        }
        __syncthreads();
        if (gp && s + 1 < T_) {
            const float4* src = (const float4*)(g_xg2 + ((size_t)(t + tstep) * B_ + b0) * 168 + dir * 84);
            #pragma unroll
            for (int q = 0; q < 4; ++q) gpre[q] = src[gb[q] * 42 + gc[q]];
        }
        if (tid < 192) {
            ulonglong2 acc[TB];
            #pragma unroll
            for (int r = 0; r < TB; ++r) {
                float4 g4 = gSd[(sg * TB + r) * 24 + jc];
                acc[r] = *reinterpret_cast<ulonglong2*>(&g4);
            }
            const ulonglong2* sWp = (const ulonglong2*)sW;
            #pragma unroll
            for (int kk = 0; kk < K4; kk += 4) {
                float4 a4[TB];
                #pragma unroll
                for (int r = 0; r < TB; ++r)
                    a4[r] = *(const float4*)(arow + r * KP + kk);
                #pragma unroll
                for (int u = 0; u < 4; ++u) {
                    ulonglong2 w = sWp[(kk + u) * NJC + jc];
                    #pragma unroll
                    for (int r = 0; r < TB; ++r) {
                        float a = reinterpret_cast<const float*>(&a4[r])[u];
                        unsigned long long ad = pk2(a, a);
                        acc[r].x = fma2_(ad, w.x, acc[r].x);
                        acc[r].y = fma2_(ad, w.y, acc[r].y);
                    }
                }
            }
            #pragma unroll
            for (int r = 0; r < TB; ++r)
                gSd[(sg * TB + r) * 24 + jc] = *reinterpret_cast<float4*>(&acc[r]);
        }
        __syncthreads();

        float* orow = g_h2 + ((size_t)t * B_ + b0) * (2 * H2_) + dir * H;
        const float* gbase = gS + p * 32 * GP;
        for (int i = 0; i < nact; ++i) {
            int b = actB[i], h = actH[i], idx = b * H + h;
            const float* grow = gbase + b * GP;
            float c = fsigm(grow[H + h]) * cS[idx] + fsigm(grow[h]) * ftanh_(grow[2 * H + h]);
            cS[idx] = c;
            float hn = fsigm(grow[3 * H + h]) * ftanh_(c);
            aS[b * KP + h] = hn;
            orow[b * (2 * H2_) + h] = hn;
        }
    }
}

// ================= dense head (smem-staged rows) =================
__global__ __launch_bounds__(256)
void dense_kernel(const float* __restrict__ wd1, const float* __restrict__ bd1,
                  const float* __restrict__ wd2, const float* __restrict__ bd2,
                  const float* __restrict__ wo,  const float* __restrict__ bo,
                  float* __restrict__ out)
{
    constexpr int IN = 2 * H2_;  // 42
    extern __shared__ float sm[];
    float* sIn = sm;                    // [256][42]
    float* s1  = sIn + 256 * IN;        // [30][42]
    float* sb1 = s1 + D1_ * IN;
    float* s2  = sb1 + D1_;             // [20][30]
    float* sb2 = s2 + D2_ * D1_;
    float* sWo = sb2 + D2_;
    float* sBo = sWo + D2_;

    const int tid = threadIdx.x;
    const size_t row0 = (size_t)blockIdx.x * 256;

    {
        const float4* src = (const float4*)(g_h2 + row0 * IN);
        float4* dst = (float4*)sIn;
        for (int i = tid; i < 256 * IN / 4; i += 256) dst[i] = src[i];
    }
    for (int i = tid; i < D1_ * IN; i += 256) s1[i] = wd1[i];
    for (int i = tid; i < D2_ * D1_; i += 256) s2[i] = wd2[i];
    if (tid < D1_) sb1[tid] = bd1[tid];
    if (tid < D2_) { sb2[tid] = bd2[tid]; sWo[tid] = wo[tid]; }
    if (tid == 0) sBo[0] = bo[0];
    __syncthreads();

    const float* in = sIn + tid * IN;
    float acc2[D2_];
    #pragma unroll
    for (int k = 0; k < D2_; ++k) acc2[k] = sb2[k];
    #pragma unroll 2
    for (int j = 0; j < D1_; ++j) {
        float v = sb1[j];
        #pragma unroll
        for (int k = 0; k < IN; ++k) v = fmaf(in[k], s1[j * IN + k], v);
        v = fmaxf(v, 0.f);
        #pragma unroll
        for (int k = 0; k < D2_; ++k) acc2[k] = fmaf(v, s2[k * D1_ + j], acc2[k]);
    }
    float y = sBo[0];
    #pragma unroll
    for (int k = 0; k < D2_; ++k) y = fmaf(fmaxf(acc2[k], 0.f), sWo[k], y);

    size_t gid = row0 + tid;          // gid = t*B + b
    int b = (int)(gid % B_), t = (int)(gid / B_);
    out[(size_t)b * T_ + t] = y;
}

// ---------------- host glue ----------------
extern "C" void kernel_launch(void* const* d_in, const int* in_sizes, int n_in,
                              void* d_out, int out_size)
{
    const float* x      = (const float*)d_in[0];
    const float* w1f_ih = (const float*)d_in[1];
    const float* w1f_hh = (const float*)d_in[2];
    const float* b1f_ih = (const float*)d_in[3];
    const float* b1f_hh = (const float*)d_in[4];
    const float* w1b_ih = (const float*)d_in[5];
    const float* w1b_hh = (const float*)d_in[6];
    const float* b1b_ih = (const float*)d_in[7];
    const float* b1b_hh = (const float*)d_in[8];
    const float* w2f_ih = (const float*)d_in[9];
    const float* w2f_hh = (const float*)d_in[10];
    const float* b2f_ih = (const float*)d_in[11];
    const float* b2f_hh = (const float*)d_in[12];
    const float* w2b_ih = (const float*)d_in[13];
    const float* w2b_hh = (const float*)d_in[14];
    const float* b2b_ih = (const float*)d_in[15];
    const float* b2b_hh = (const float*)d_in[16];
    const float* wd1    = (const float*)d_in[17];
    const float* bd1    = (const float*)d_in[18];
    const float* wd2    = (const float*)d_in[19];
    const float* bd2    = (const float*)d_in[20];
    const float* wo     = (const float*)d_in[21];
    const float* bo     = (const float*)d_in[22];
    float* out = (float*)d_out;

    const int SM1 = (80 * 288 + 32 * 288 + 32 * 84 + 32 * 70 + 288) * 4;   // 149888
    const int SMX = (140 * 168 + 64 * 144 + 168) * 4;                      // 131616
    const int SM2 = (24 * 96 + 2 * 32 * 96 + 32 * 28 + 32 * 21) * 4;       // 40064
    const int SMD = (256 * 42 + 30 * 42 + 30 + 20 * 30 + 20 + 20 + 1) * 4; // 50732

    cudaFuncSetAttribute(lstm1_kernel, cudaFuncAttributeMaxDynamicSharedMemorySize, SM1);
    cudaFuncSetAttribute(xg2_kernel,   cudaFuncAttributeMaxDynamicSharedMemorySize, SMX);
    cudaFuncSetAttribute(lstm2_kernel, cudaFuncAttributeMaxDynamicSharedMemorySize, SM2);
    cudaFuncSetAttribute(dense_kernel, cudaFuncAttributeMaxDynamicSharedMemorySize, SMD);

    transpose_x<<<(B_ * T_ * F_ + 255) / 256, 256>>>(x);
    prep_w2<<<(168 * 140 + 255) / 256, 256>>>(w2f_ih, w2b_ih, b2f_ih, b2f_hh, b2b_ih, b2b_hh);

    lstm1_kernel<<<dim3(B_ / 32, 2), 288, SM1>>>(
        w1f_ih, w1f_hh, b1f_ih, b1f_hh,
        w1b_ih, w1b_hh, b1b_ih, b1b_hh);

    xg2_kernel<<<(T_ * B_) / 64, 352, SMX>>>();

    lstm2_kernel<<<dim3(B_ / 32, 2), 256, SM2>>>(w2f_hh, w2b_hh);

    dense_kernel<<<(T_ * B_) / 256, 256, SMD>>>(wd1, bd1, wd2, bd2, wo, bo, out);
}

// round 4
// speedup vs baseline: 1.9830x; 1.3362x over previous
#include <cuda_runtime.h>
#include <cstdint>

#define B_  2048
#define T_  336
#define F_  10
#define H1_ 70
#define H2_ 21
#define D1_ 30
#define D2_ 20

typedef unsigned long long u64;

// ---------------- scratch (__device__ globals; no allocations) ----------------
__device__ float g_xT [(size_t)T_ * B_ * F_];          // x transposed [T][B][10]
__device__ float g_h1 [(size_t)T_ * B_ * (2*H1_)];     // layer1 out   [T][B][140]
__device__ float g_xg2[(size_t)T_ * B_ * (8*H2_)];     // layer2 input gates [T][B][168]
__device__ float g_h2 [(size_t)T_ * B_ * (2*H2_)];     // layer2 out   [T][B][42]
__device__ float g_w2t[140 * 168];                     // W2_ih^T packed, both dirs
__device__ float g_b2 [168];

// ---------------- packed f32x2 fma ----------------
__device__ __forceinline__ u64 fma2_(u64 a, u64 b, u64 c) {
    u64 d;
    asm("fma.rn.f32x2 %0, %1, %2, %3;" : "=l"(d) : "l"(a), "l"(b), "l"(c));
    return d;
}

// ---------------- activations (accurate fast-math, ~1e-6 rel) ----------------
__device__ __forceinline__ float fsigm(float x) {
    return __fdividef(1.f, 1.f + __expf(-x));
}
__device__ __forceinline__ float ftanh_(float x) {
    return 1.f - 2.f * __fdividef(1.f, 1.f + __expf(2.f * x));
}

// ---------------- transpose x: [B][T][F] -> [T][B][F] ----------------
__global__ void transpose_x(const float* __restrict__ x) {
    int gid = blockIdx.x * blockDim.x + threadIdx.x;
    if (gid < B_ * T_ * F_) {
        int f = gid % F_;
        int t = (gid / F_) % T_;
        int b = gid / (F_ * T_);
        g_xT[((size_t)t * B_ + b) * F_ + f] = x[gid];
    }
}

// ---------------- prep: transpose layer-2 input weights to k-major ----------------
__global__ void prep_w2(const float* __restrict__ wf, const float* __restrict__ wb,
                        const float* __restrict__ bfi, const float* __restrict__ bfh,
                        const float* __restrict__ bbi, const float* __restrict__ bbh) {
    int i = blockIdx.x * blockDim.x + threadIdx.x;
    if (i < 168 * 140) {
        int jj = i / 140;
        int k  = i % 140;
        int dir = jj / 84, j = jj % 84;
        const float* w = dir ? wb : wf;
        g_w2t[k * 168 + jj] = w[j * 140 + k];
    }
    if (i < 168) {
        int dir = i / 84, j = i % 84;
        g_b2[i] = dir ? (bbi[j] + bbh[j]) : (bfi[j] + bfh[j]);
    }
}

// ================= layer 1: fused-input recurrent LSTM =================
// block = 32 samples x 1 direction; K = 10(x)+70(h) = 80 (pairs, pitch 82);
// gates G=280 padded to 288; 288 threads = 4 sample-groups x 72 float4 chunks.
__global__ __launch_bounds__(288, 1)
void lstm1_kernel(const float* __restrict__ Wih_f, const float* __restrict__ Whh_f,
                  const float* __restrict__ bih_f, const float* __restrict__ bhh_f,
                  const float* __restrict__ Wih_b, const float* __restrict__ Whh_b,
                  const float* __restrict__ bih_b, const float* __restrict__ bhh_b)
{
    constexpr int I = 10, H = 70, K = 80, KP2 = 82, G = 280, GP = 288, NJC = 72, TB = 8;
    extern __shared__ float sm[];
    float* sW = sm;                    // [80][288] k-major
    float* gS = sW + K * GP;           // [32][288]
    float* aS = gS + 32 * GP;          // [32][82] duplicated pairs (float2)
    float* cS = aS + 32 * KP2 * 2;     // [32][70]
    float* sb = cS + 32 * H;           // [288]

    const int dir = blockIdx.y;
    const float* Wih = dir ? Wih_b : Wih_f;
    const float* Whh = dir ? Whh_b : Whh_f;
    const float* bih = dir ? bih_b : bih_f;
    const float* bhh = dir ? bhh_b : bhh_f;
    const int b0  = blockIdx.x * 32;
    const int tid = threadIdx.x;

    for (int idx = tid; idx < K * GP; idx += 288) {
        int k = idx / GP, j = idx % GP;
        float v = 0.f;
        if (j < G) v = (k < I) ? Wih[j * I + k] : Whh[j * H + (k - I)];
        sW[idx] = v;
    }
    for (int j = tid; j < GP; j += 288) sb[j] = (j < G) ? (bih[j] + bhh[j]) : 0.f;
    for (int idx = tid; idx < 32 * KP2 * 2; idx += 288) aS[idx] = 0.f;
    for (int idx = tid; idx < 32 * H; idx += 288) cS[idx] = 0.f;

    // x staging map: tid<80, 4 consecutive floats of the 320-float x block
    const bool xp = tid < 80;
    const int xb0 = (tid * 4) / I, xk0 = (tid * 4) % I;
    // activation map: tid<280, 8 consecutive of 2240 elems
    const bool ap = tid < 280;
    const int ab0 = (tid * 8) / H, ah0 = (tid * 8) % H;

    const int sg = tid / NJC, jc = tid % NJC;
    const u64* arow = ((const u64*)aS) + (size_t)(sg * TB) * KP2;
    const ulonglong2* sWp = (const ulonglong2*)sW;

    int t = dir ? (T_ - 1) : 0;
    const int tstep = dir ? -1 : 1;
    float4 xpre = make_float4(0.f, 0.f, 0.f, 0.f);
    if (xp) xpre = ((const float4*)(g_xT + ((size_t)t * B_ + b0) * I))[tid];
    __syncthreads();

    for (int s = 0; s < T_; ++s, t += tstep) {
        // ---- stage x_t as duplicated pairs ----
        if (xp) {
            float xv[4] = {xpre.x, xpre.y, xpre.z, xpre.w};
            int b = xb0, k = xk0;
            #pragma unroll
            for (int c = 0; c < 4; ++c) {
                ((float2*)aS)[b * KP2 + k] = make_float2(xv[c], xv[c]);
                if (++k == I) { k = 0; ++b; }
            }
        }
        __syncthreads();
        if (xp && s + 1 < T_)
            xpre = ((const float4*)(g_xT + ((size_t)(t + tstep) * B_ + b0) * I))[tid];

        // ---- packed matvec: g = bias + [x|h] @ W ----
        {
            float4 b4 = ((const float4*)sb)[jc];
            ulonglong2 binit = *reinterpret_cast<ulonglong2*>(&b4);
            ulonglong2 acc[TB];
            #pragma unroll
            for (int r = 0; r < TB; ++r) acc[r] = binit;

            #pragma unroll 4
            for (int kk = 0; kk < K; kk += 2) {
                ulonglong2 w0 = sWp[kk * NJC + jc];
                ulonglong2 w1 = sWp[(kk + 1) * NJC + jc];
                #pragma unroll
                for (int r = 0; r < TB; ++r) {
                    ulonglong2 a = *(const ulonglong2*)(arow + r * KP2 + kk);
                    acc[r].x = fma2_(a.x, w0.x, acc[r].x);
                    acc[r].y = fma2_(a.x, w0.y, acc[r].y);
                    acc[r].x = fma2_(a.y, w1.x, acc[r].x);
                    acc[r].y = fma2_(a.y, w1.y, acc[r].y);
                }
            }
            ulonglong2* gSp = (ulonglong2*)gS;
            #pragma unroll
            for (int r = 0; r < TB; ++r) gSp[(sg * TB + r) * NJC + jc] = acc[r];
        }
        __syncthreads();

        // ---- gates + state update + h store ----
        if (ap) {
            float* orow = g_h1 + ((size_t)t * B_ + b0) * (2 * H1_) + dir * H;
            int b = ab0, h = ah0;
            #pragma unroll
            for (int j = 0; j < 8; ++j) {
                const float* grow = gS + b * GP;
                int ci = b * H + h;
                float c = fsigm(grow[H + h]) * cS[ci] + fsigm(grow[h]) * ftanh_(grow[2 * H + h]);
                cS[ci] = c;
                float hn = fsigm(grow[3 * H + h]) * ftanh_(c);
                ((float2*)aS)[b * KP2 + I + h] = make_float2(hn, hn);
                orow[b * (2 * H1_) + h] = hn;
                if (++h == H) { h = 0; ++b; }
            }
        }
    }
}

// ================= layer-2 input GEMM: xg2 = h1 @ W2ih^T + biases =================
// block = 96 rows; K=140 (pairs, pitch 142), G=168; 512 threads (12 sg x 42 chunks = 504 workers)
__global__ __launch_bounds__(512, 1)
void xg2_kernel()
{
    constexpr int BB = 96, K = 140, KP2 = 142, G = 168, NJC = 42, TB = 8;
    extern __shared__ float sm[];
    float* sW = sm;                 // [140][168]
    float* aS = sW + K * G;         // [96][142] duplicated pairs
    float* sb = aS + BB * KP2 * 2;  // [168]
    const int tid = threadIdx.x;
    const size_t row0 = (size_t)blockIdx.x * BB;

    {
        const float4* wsrc = (const float4*)g_w2t;
        float4* wdst = (float4*)sW;
        for (int i = tid; i < K * G / 4; i += 512) wdst[i] = wsrc[i];
    }
    for (int j = tid; j < G; j += 512) sb[j] = g_b2[j];
    {
        const float4* src = (const float4*)(g_h1 + row0 * K);
        for (int i = tid; i < BB * K / 4; i += 512) {
            int r = i / 35, c4 = i % 35;          // 35 float4 per 140-float row
            float4 v = src[i];
            float2* d = ((float2*)aS) + r * KP2 + c4 * 4;
            d[0] = make_float2(v.x, v.x);
            d[1] = make_float2(v.y, v.y);
            d[2] = make_float2(v.z, v.z);
            d[3] = make_float2(v.w, v.w);
        }
    }
    __syncthreads();

    if (tid < 504) {
        const int sg = tid / NJC, jc = tid % NJC;
        const u64* arow = ((const u64*)aS) + (size_t)(sg * TB) * KP2;
        const ulonglong2* sWp = (const ulonglong2*)sW;
        float4 b4 = ((const float4*)sb)[jc];
        ulonglong2 binit = *reinterpret_cast<ulonglong2*>(&b4);
        ulonglong2 acc[TB];
        #pragma unroll
        for (int r = 0; r < TB; ++r) acc[r] = binit;

        #pragma unroll 4
        for (int kk = 0; kk < K; kk += 2) {
            ulonglong2 w0 = sWp[kk * NJC + jc];
            ulonglong2 w1 = sWp[(kk + 1) * NJC + jc];
            #pragma unroll
            for (int r = 0; r < TB; ++r) {
                ulonglong2 a = *(const ulonglong2*)(arow + r * KP2 + kk);
                acc[r].x = fma2_(a.x, w0.x, acc[r].x);
                acc[r].y = fma2_(a.x, w0.y, acc[r].y);
                acc[r].x = fma2_(a.y, w1.x, acc[r].x);
                acc[r].y = fma2_(a.y, w1.y, acc[r].y);
            }
        }
        float4* outp = (float4*)(g_xg2 + row0 * G);
        #pragma unroll
        for (int r = 0; r < TB; ++r)
            outp[(sg * TB + r) * NJC + jc] = *reinterpret_cast<float4*>(&acc[r]);
    }
}

// ================= layer 2: recurrent-only LSTM (K = 21, padded 24) =================
__global__ __launch_bounds__(256, 1)
void lstm2_kernel(const float* __restrict__ Whh_f, const float* __restrict__ Whh_b)
{
    constexpr int H = 21, KPAD = 24, KP2 = 24, G = 84, GP = 96, NJC = 24, TB = 4;
    extern __shared__ float sm[];
    float* sW = sm;                 // [24][96]
    float* gS = sW + KPAD * GP;     // [2][32][96] double-buffered
    float* aS = gS + 2 * 32 * GP;   // [32][24] duplicated pairs
    float* cS = aS + 32 * KP2 * 2;  // [32][21]

    const int dir = blockIdx.y;
    const float* Whh = dir ? Whh_b : Whh_f;
    const int b0  = blockIdx.x * 32;
    const int tid = threadIdx.x;

    for (int idx = tid; idx < KPAD * GP; idx += 256) {
        int k = idx / GP, j = idx % GP;
        sW[idx] = (k < H && j < G) ? Whh[j * H + k] : 0.f;
    }
    for (int idx = tid; idx < 32 * KP2 * 2; idx += 256) aS[idx] = 0.f;
    for (int idx = tid; idx < 32 * H; idx += 256) cS[idx] = 0.f;

    // g prefetch mapping: 672 float4, tid<168 loads 4 each
    const bool gp = tid < 168;
    int gb[4] = {0,0,0,0}, gc[4] = {0,0,0,0};
    if (gp) {
        #pragma unroll
        for (int q = 0; q < 4; ++q) { int i = tid * 4 + q; gb[q] = i / 21; gc[q] = i % 21; }
    }
    // act mapping: tid<168, 4 consecutive of 672 elems
    const bool ap = tid < 168;
    const int ab0 = (tid * 4) / H, ah0 = (tid * 4) % H;

    const int sg = tid / NJC, jc = tid % NJC;
    const u64* arow = ((const u64*)aS) + (size_t)(sg * TB) * KP2;
    const ulonglong2* sWp = (const ulonglong2*)sW;

    int t = dir ? (T_ - 1) : 0;
    const int tstep = dir ? -1 : 1;
    float4 gpre[4];
    if (gp) {
        const float4* src = (const float4*)(g_xg2 + ((size_t)t * B_ + b0) * 168 + dir * 84);
        #pragma unroll
        for (int q = 0; q < 4; ++q) gpre[q] = src[gb[q] * 42 + gc[q]];
    }
    __syncthreads();

    for (int s = 0; s < T_; ++s, t += tstep) {
        const int p = s & 1;
        float4* gSd = (float4*)(gS + p * 32 * GP);
        if (gp) {
            #pragma unroll
            for (int q = 0; q < 4; ++q) gSd[gb[q] * 24 + gc[q]] = gpre[q];
        }
        __syncthreads();
        if (gp && s + 1 < T_) {
            const float4* src = (const float4*)(g_xg2 + ((size_t)(t + tstep) * B_ + b0) * 168 + dir * 84);
            #pragma unroll
            for (int q = 0; q < 4; ++q) gpre[q] = src[gb[q] * 42 + gc[q]];
        }
        if (tid < 192) {
            ulonglong2 acc[TB];
            #pragma unroll
            for (int r = 0; r < TB; ++r) {
                float4 g4 = gSd[(sg * TB + r) * 24 + jc];
                acc[r] = *reinterpret_cast<ulonglong2*>(&g4);
            }
            #pragma unroll
            for (int kk = 0; kk < KPAD; kk += 2) {
                ulonglong2 w0 = sWp[kk * NJC + jc];
                ulonglong2 w1 = sWp[(kk + 1) * NJC + jc];
                #pragma unroll
                for (int r = 0; r < TB; ++r) {
                    ulonglong2 a = *(const ulonglong2*)(arow + r * KP2 + kk);
                    acc[r].x = fma2_(a.x, w0.x, acc[r].x);
                    acc[r].y = fma2_(a.x, w0.y, acc[r].y);
                    acc[r].x = fma2_(a.y, w1.x, acc[r].x);
                    acc[r].y = fma2_(a.y, w1.y, acc[r].y);
                }
            }
            #pragma unroll
            for (int r = 0; r < TB; ++r)
                gSd[(sg * TB + r) * 24 + jc] = *reinterpret_cast<float4*>(&acc[r]);
        }
        __syncthreads();

        if (ap) {
            float* orow = g_h2 + ((size_t)t * B_ + b0) * (2 * H2_) + dir * H;
            const float* gbase = gS + p * 32 * GP;
            int b = ab0, h = ah0;
            #pragma unroll
            for (int j = 0; j < 4; ++j) {
                const float* grow = gbase + b * GP;
                int ci = b * H + h;
                float c = fsigm(grow[H + h]) * cS[ci] + fsigm(grow[h]) * ftanh_(grow[2 * H + h]);
                cS[ci] = c;
                float hn = fsigm(grow[3 * H + h]) * ftanh_(c);
                ((float2*)aS)[b * KP2 + h] = make_float2(hn, hn);
                orow[b * (2 * H2_) + h] = hn;
                if (++h == H) { h = 0; ++b; }
            }
        }
    }
}

// ================= dense head (smem-staged rows) =================
__global__ __launch_bounds__(256)
void dense_kernel(const float* __restrict__ wd1, const float* __restrict__ bd1,
                  const float* __restrict__ wd2, const float* __restrict__ bd2,
                  const float* __restrict__ wo,  const float* __restrict__ bo,
                  float* __restrict__ out)
{
    constexpr int IN = 2 * H2_;  // 42
    extern __shared__ float sm[];
    float* sIn = sm;                    // [256][42]
    float* s1  = sIn + 256 * IN;        // [30][42]
    float* sb1 = s1 + D1_ * IN;
    float* s2  = sb1 + D1_;             // [20][30]
    float* sb2 = s2 + D2_ * D1_;
    float* sWo = sb2 + D2_;
    float* sBo = sWo + D2_;

    const int tid = threadIdx.x;
    const size_t row0 = (size_t)blockIdx.x * 256;

    {
        const float4* src = (const float4*)(g_h2 + row0 * IN);
        float4* dst = (float4*)sIn;
        for (int i = tid; i < 256 * IN / 4; i += 256) dst[i] = src[i];
    }
    for (int i = tid; i < D1_ * IN; i += 256) s1[i] = wd1[i];
    for (int i = tid; i < D2_ * D1_; i += 256) s2[i] = wd2[i];
    if (tid < D1_) sb1[tid] = bd1[tid];
    if (tid < D2_) { sb2[tid] = bd2[tid]; sWo[tid] = wo[tid]; }
    if (tid == 0) sBo[0] = bo[0];
    __syncthreads();

    const float* in = sIn + tid * IN;
    float acc2[D2_];
    #pragma unroll
    for (int k = 0; k < D2_; ++k) acc2[k] = sb2[k];
    #pragma unroll 2
    for (int j = 0; j < D1_; ++j) {
        float v = sb1[j];
        #pragma unroll
        for (int k = 0; k < IN; ++k) v = fmaf(in[k], s1[j * IN + k], v);
        v = fmaxf(v, 0.f);
        #pragma unroll
        for (int k = 0; k < D2_; ++k) acc2[k] = fmaf(v, s2[k * D1_ + j], acc2[k]);
    }
    float y = sBo[0];
    #pragma unroll
    for (int k = 0; k < D2_; ++k) y = fmaf(fmaxf(acc2[k], 0.f), sWo[k], y);

    size_t gid = row0 + tid;          // gid = t*B + b
    int b = (int)(gid % B_), t = (int)(gid / B_);
    out[(size_t)b * T_ + t] = y;
}

// ---------------- host glue ----------------
extern "C" void kernel_launch(void* const* d_in, const int* in_sizes, int n_in,
                              void* d_out, int out_size)
{
    const float* x      = (const float*)d_in[0];
    const float* w1f_ih = (const float*)d_in[1];
    const float* w1f_hh = (const float*)d_in[2];
    const float* b1f_ih = (const float*)d_in[3];
    const float* b1f_hh = (const float*)d_in[4];
    const float* w1b_ih = (const float*)d_in[5];
    const float* w1b_hh = (const float*)d_in[6];
    const float* b1b_ih = (const float*)d_in[7];
    const float* b1b_hh = (const float*)d_in[8];
    const float* w2f_ih = (const float*)d_in[9];
    const float* w2f_hh = (const float*)d_in[10];
    const float* b2f_ih = (const float*)d_in[11];
    const float* b2f_hh = (const float*)d_in[12];
    const float* w2b_ih = (const float*)d_in[13];
    const float* w2b_hh = (const float*)d_in[14];
    const float* b2b_ih = (const float*)d_in[15];
    const float* b2b_hh = (const float*)d_in[16];
    const float* wd1    = (const float*)d_in[17];
    const float* bd1    = (const float*)d_in[18];
    const float* wd2    = (const float*)d_in[19];
    const float* bd2    = (const float*)d_in[20];
    const float* wo     = (const float*)d_in[21];
    const float* bo     = (const float*)d_in[22];
    float* out = (float*)d_out;

    const int SM1 = (80 * 288 + 32 * 288 + 32 * 82 * 2 + 32 * 70 + 288) * 4;  // 160128
    const int SMX = (140 * 168 + 96 * 142 * 2 + 168) * 4;                     // 203808
    const int SM2 = (24 * 96 + 2 * 32 * 96 + 32 * 24 * 2 + 32 * 21) * 4;      // 42624
    const int SMD = (256 * 42 + 30 * 42 + 30 + 20 * 30 + 20 + 20 + 1) * 4;    // 50732

    cudaFuncSetAttribute(lstm1_kernel, cudaFuncAttributeMaxDynamicSharedMemorySize, SM1);
    cudaFuncSetAttribute(xg2_kernel,   cudaFuncAttributeMaxDynamicSharedMemorySize, SMX);
    cudaFuncSetAttribute(lstm2_kernel, cudaFuncAttributeMaxDynamicSharedMemorySize, SM2);
    cudaFuncSetAttribute(dense_kernel, cudaFuncAttributeMaxDynamicSharedMemorySize, SMD);

    transpose_x<<<(B_ * T_ * F_ + 255) / 256, 256>>>(x);
    prep_w2<<<(168 * 140 + 255) / 256, 256>>>(w2f_ih, w2b_ih, b2f_ih, b2f_hh, b2b_ih, b2b_hh);

    lstm1_kernel<<<dim3(B_ / 32, 2), 288, SM1>>>(
        w1f_ih, w1f_hh, b1f_ih, b1f_hh,
        w1b_ih, w1b_hh, b1b_ih, b1b_hh);

    xg2_kernel<<<(T_ * B_) / 96, 512, SMX>>>();

    lstm2_kernel<<<dim3(B_ / 32, 2), 256, SM2>>>(w2f_hh, w2b_hh);

    dense_kernel<<<(T_ * B_) / 256, 256, SMD>>>(wd1, bd1, wd2, bd2, wo, bo, out);
}

// round 5
// speedup vs baseline: 1.9905x; 1.0038x over previous
#include <cuda_runtime.h>
#include <cstdint>

#define B_  2048
#define T_  336
#define F_  10
#define H1_ 70
#define H2_ 21
#define D1_ 30
#define D2_ 20

typedef unsigned long long u64;

// ---------------- scratch (__device__ globals; no allocations) ----------------
__device__ float g_xT [(size_t)T_ * B_ * F_];          // x transposed [T][B][10]
__device__ float g_h1 [(size_t)T_ * B_ * (2*H1_)];     // layer1 out   [T][B][140]
__device__ float g_xg2[(size_t)T_ * B_ * (8*H2_)];     // layer2 input gates [T][B][168]
__device__ float g_h2 [(size_t)T_ * B_ * (2*H2_)];     // layer2 out   [T][B][42]
__device__ float g_y  [(size_t)T_ * B_];               // head out, t-major
__device__ float g_w2t[140 * 168];                     // W2_ih^T packed, both dirs
__device__ float g_b2 [168];

// ---------------- packed f32x2 fma ----------------
__device__ __forceinline__ u64 fma2_(u64 a, u64 b, u64 c) {
    u64 d;
    asm("fma.rn.f32x2 %0, %1, %2, %3;" : "=l"(d) : "l"(a), "l"(b), "l"(c));
    return d;
}

// ---------------- activations (accurate fast-math, ~1e-6 rel) ----------------
__device__ __forceinline__ float fsigm(float x) {
    return __fdividef(1.f, 1.f + __expf(-x));
}
__device__ __forceinline__ float ftanh_(float x) {
    return 1.f - 2.f * __fdividef(1.f, 1.f + __expf(2.f * x));
}

// ---------------- transpose x: [B][T][F] -> [T][B][F] ----------------
__global__ void transpose_x(const float* __restrict__ x) {
    int gid = blockIdx.x * blockDim.x + threadIdx.x;
    if (gid < B_ * T_ * F_) {
        int f = gid % F_;
        int t = (gid / F_) % T_;
        int b = gid / (F_ * T_);
        g_xT[((size_t)t * B_ + b) * F_ + f] = x[gid];
    }
}

// ---------------- prep: transpose layer-2 input weights to k-major ----------------
__global__ void prep_w2(const float* __restrict__ wf, const float* __restrict__ wb,
                        const float* __restrict__ bfi, const float* __restrict__ bfh,
                        const float* __restrict__ bbi, const float* __restrict__ bbh) {
    int i = blockIdx.x * blockDim.x + threadIdx.x;
    if (i < 168 * 140) {
        int jj = i / 140;
        int k  = i % 140;
        int dir = jj / 84, j = jj % 84;
        const float* w = dir ? wb : wf;
        g_w2t[k * 168 + jj] = w[j * 140 + k];
    }
    if (i < 168) {
        int dir = i / 84, j = i % 84;
        g_b2[i] = dir ? (bbi[j] + bbh[j]) : (bfi[j] + bfh[j]);
    }
}

// ================= layer 1: fused-input recurrent LSTM =================
// block = 32 samples x 1 direction; K = 10(x)+70(h) pairs (pitch 82 pairs);
// gates G=280 padded to 288; 288 threads = 4 sample-groups x 72 float4 chunks.
__global__ __launch_bounds__(288, 1)
void lstm1_kernel(const float* __restrict__ Wih_f, const float* __restrict__ Whh_f,
                  const float* __restrict__ bih_f, const float* __restrict__ bhh_f,
                  const float* __restrict__ Wih_b, const float* __restrict__ Whh_b,
                  const float* __restrict__ bih_b, const float* __restrict__ bhh_b)
{
    constexpr int I = 10, H = 70, K = 80, KP2 = 82, G = 280, GP = 288, NJC = 72, TB = 8;
    extern __shared__ float sm[];
    float* sW = sm;                    // [80][288] k-major
    float* gS = sW + K * GP;           // [32][288]
    float* aS = gS + 32 * GP;          // [32][82] duplicated pairs (float2)
    float* cS = aS + 32 * KP2 * 2;     // [32][70]
    float* sb = cS + 32 * H;           // [288]

    const int dir = blockIdx.y;
    const float* Wih = dir ? Wih_b : Wih_f;
    const float* Whh = dir ? Whh_b : Whh_f;
    const float* bih = dir ? bih_b : bih_f;
    const float* bhh = dir ? bhh_b : bhh_f;
    const int b0  = blockIdx.x * 32;
    const int tid = threadIdx.x;

    for (int idx = tid; idx < K * GP; idx += 288) {
        int k = idx / GP, j = idx % GP;
        float v = 0.f;
        if (j < G) v = (k < I) ? Wih[j * I + k] : Whh[j * H + (k - I)];
        sW[idx] = v;
    }
    for (int j = tid; j < GP; j += 288) sb[j] = (j < G) ? (bih[j] + bhh[j]) : 0.f;
    for (int idx = tid; idx < 32 * KP2 * 2; idx += 288) aS[idx] = 0.f;
    for (int idx = tid; idx < 32 * H; idx += 288) cS[idx] = 0.f;

    // x staging map (element-consecutive, conflict-free): e=tid and e2=288+tid
    const int xb0 = tid / I,        xk0 = tid % I;
    const int xb1 = (288 + tid) / I, xk1 = (288 + tid) % I;
    const bool xp1v = tid < 32;     // 320 x floats total
    // activation map start (element-consecutive)
    const int ab0 = tid / H, ah0 = tid % H;

    const int sg = tid / NJC, jc = tid % NJC;
    const u64* arow = ((const u64*)aS) + (size_t)(sg * TB) * KP2;
    const ulonglong2* sWp = (const ulonglong2*)sW;

    int t = dir ? (T_ - 1) : 0;
    const int tstep = dir ? -1 : 1;
    float xp0 = 0.f, xp1 = 0.f;
    {
        const float* xr = g_xT + ((size_t)t * B_ + b0) * I;
        xp0 = xr[tid];
        if (xp1v) xp1 = xr[288 + tid];
    }
    __syncthreads();

    for (int s = 0; s < T_; ++s, t += tstep) {
        // ---- stage x_t as duplicated pairs (stride-1 across lanes) ----
        ((float2*)aS)[xb0 * KP2 + xk0] = make_float2(xp0, xp0);
        if (xp1v) ((float2*)aS)[xb1 * KP2 + xk1] = make_float2(xp1, xp1);
        __syncthreads();
        if (s + 1 < T_) {
            const float* xr = g_xT + ((size_t)(t + tstep) * B_ + b0) * I;
            xp0 = xr[tid];
            if (xp1v) xp1 = xr[288 + tid];
        }

        // ---- packed matvec: g = bias + [x|h] @ W ----
        {
            float4 b4 = ((const float4*)sb)[jc];
            ulonglong2 binit = *reinterpret_cast<ulonglong2*>(&b4);
            ulonglong2 acc[TB];
            #pragma unroll
            for (int r = 0; r < TB; ++r) acc[r] = binit;

            #pragma unroll 4
            for (int kk = 0; kk < K; kk += 2) {
                ulonglong2 w0 = sWp[kk * NJC + jc];
                ulonglong2 w1 = sWp[(kk + 1) * NJC + jc];
                #pragma unroll
                for (int r = 0; r < TB; ++r) {
                    ulonglong2 a = *(const ulonglong2*)(arow + r * KP2 + kk);
                    acc[r].x = fma2_(a.x, w0.x, acc[r].x);
                    acc[r].y = fma2_(a.x, w0.y, acc[r].y);
                    acc[r].x = fma2_(a.y, w1.x, acc[r].x);
                    acc[r].y = fma2_(a.y, w1.y, acc[r].y);
                }
            }
            ulonglong2* gSp = (ulonglong2*)gS;
            #pragma unroll
            for (int r = 0; r < TB; ++r) gSp[(sg * TB + r) * NJC + jc] = acc[r];
        }
        __syncthreads();

        // ---- gates + state update + h store (element-consecutive, conflict-free) ----
        {
            float* orow = g_h1 + ((size_t)t * B_ + b0) * (2 * H1_) + dir * H;
            int b = ab0, h = ah0;
            for (int e = tid; e < 32 * H; e += 288) {
                const float* grow = gS + b * GP;
                float c = fsigm(grow[H + h]) * cS[e] + fsigm(grow[h]) * ftanh_(grow[2 * H + h]);
                cS[e] = c;
                float hn = fsigm(grow[3 * H + h]) * ftanh_(c);
                ((float2*)aS)[b * KP2 + I + h] = make_float2(hn, hn);
                orow[b * (2 * H1_) + h] = hn;
                b += 4; h += 8; if (h >= H) { h -= H; ++b; }
            }
        }
    }
}

// ================= layer-2 input GEMM: xg2 = h1 @ W2ih^T + biases =================
// block = 96 rows; K=140 (pairs, pitch 142), G=168; TB=12, NSG=8, NJC=42 -> 336 of 352 thr
__global__ __launch_bounds__(352, 1)
void xg2_kernel()
{
    constexpr int BB = 96, K = 140, KP2 = 142, G = 168, NJC = 42, TB = 12;
    extern __shared__ float sm[];
    float* sW = sm;                 // [140][168]
    float* aS = sW + K * G;         // [96][142] duplicated pairs
    float* sb = aS + BB * KP2 * 2;  // [168]
    const int tid = threadIdx.x;
    const size_t row0 = (size_t)blockIdx.x * BB;

    {
        const float4* wsrc = (const float4*)g_w2t;
        float4* wdst = (float4*)sW;
        for (int i = tid; i < K * G / 4; i += 352) wdst[i] = wsrc[i];
    }
    for (int j = tid; j < G; j += 352) sb[j] = g_b2[j];
    {
        // scalar coalesced loads, stride-1 dup-pair stores (conflict-free)
        const float* src = g_h1 + row0 * K;
        int r = tid / K, c = tid % K;
        for (int q = tid; q < BB * K; q += 352) {
            float v = src[q];
            ((float2*)aS)[r * KP2 + c] = make_float2(v, v);
            r += 2; c += 72; if (c >= K) { c -= K; ++r; }
        }
    }
    __syncthreads();

    if (tid < 336) {
        const int sg = tid / NJC, jc = tid % NJC;
        const u64* arow = ((const u64*)aS) + (size_t)(sg * TB) * KP2;
        const ulonglong2* sWp = (const ulonglong2*)sW;
        float4 b4 = ((const float4*)sb)[jc];
        ulonglong2 binit = *reinterpret_cast<ulonglong2*>(&b4);
        ulonglong2 acc[TB];
        #pragma unroll
        for (int r = 0; r < TB; ++r) acc[r] = binit;

        #pragma unroll 2
        for (int kk = 0; kk < K; kk += 2) {
            ulonglong2 w0 = sWp[kk * NJC + jc];
            ulonglong2 w1 = sWp[(kk + 1) * NJC + jc];
            #pragma unroll
            for (int r = 0; r < TB; ++r) {
                ulonglong2 a = *(const ulonglong2*)(arow + r * KP2 + kk);
                acc[r].x = fma2_(a.x, w0.x, acc[r].x);
                acc[r].y = fma2_(a.x, w0.y, acc[r].y);
                acc[r].x = fma2_(a.y, w1.x, acc[r].x);
                acc[r].y = fma2_(a.y, w1.y, acc[r].y);
            }
        }
        float4* outp = (float4*)(g_xg2 + row0 * G);
        #pragma unroll
        for (int r = 0; r < TB; ++r)
            outp[(sg * TB + r) * NJC + jc] = *reinterpret_cast<float4*>(&acc[r]);
    }
}

// ================= layer 2: recurrent-only LSTM (K = 21, padded 24) =================
__global__ __launch_bounds__(256, 1)
void lstm2_kernel(const float* __restrict__ Whh_f, const float* __restrict__ Whh_b)
{
    constexpr int H = 21, KPAD = 24, KP2 = 24, G = 84, GP = 96, NJC = 24, TB = 4;
    extern __shared__ float sm[];
    float* sW = sm;                 // [24][96]
    float* gS = sW + KPAD * GP;     // [2][32][96] double-buffered
    float* aS = gS + 2 * 32 * GP;   // [32][24] duplicated pairs
    float* cS = aS + 32 * KP2 * 2;  // [32][21]

    const int dir = blockIdx.y;
    const float* Whh = dir ? Whh_b : Whh_f;
    const int b0  = blockIdx.x * 32;
    const int tid = threadIdx.x;

    for (int idx = tid; idx < KPAD * GP; idx += 256) {
        int k = idx / GP, j = idx % GP;
        sW[idx] = (k < H && j < G) ? Whh[j * H + k] : 0.f;
    }
    for (int idx = tid; idx < 32 * KP2 * 2; idx += 256) aS[idx] = 0.f;
    for (int idx = tid; idx < 32 * H; idx += 256) cS[idx] = 0.f;

    // g staging map (element-consecutive float4): slots tid, tid+256, tid+512 of 672
    const int i1 = tid + 256, i2 = tid + 512;
    const int gb0 = tid / 21, gc0 = tid % 21;
    const int gb1 = i1 / 21,  gc1 = i1 % 21;
    const int gb2 = i2 / 21,  gc2 = i2 % 21;
    const bool v2 = i2 < 672;
    // activation map start (element-consecutive)
    const int ab0 = tid / H, ah0 = tid % H;

    const int sg = tid / NJC, jc = tid % NJC;
    const u64* arow = ((const u64*)aS) + (size_t)(sg * TB) * KP2;
    const ulonglong2* sWp = (const ulonglong2*)sW;

    int t = dir ? (T_ - 1) : 0;
    const int tstep = dir ? -1 : 1;
    float4 gp0, gp1, gp2;
    {
        const float4* src = (const float4*)(g_xg2 + ((size_t)t * B_ + b0) * 168 + dir * 84);
        gp0 = src[gb0 * 42 + gc0];
        gp1 = src[gb1 * 42 + gc1];
        if (v2) gp2 = src[gb2 * 42 + gc2];
    }
    __syncthreads();

    for (int s = 0; s < T_; ++s, t += tstep) {
        const int p = s & 1;
        float4* gSd = (float4*)(gS + p * 32 * GP);
        gSd[gb0 * 24 + gc0] = gp0;
        gSd[gb1 * 24 + gc1] = gp1;
        if (v2) gSd[gb2 * 24 + gc2] = gp2;
        __syncthreads();
        if (s + 1 < T_) {
            const float4* src = (const float4*)(g_xg2 + ((size_t)(t + tstep) * B_ + b0) * 168 + dir * 84);
            gp0 = src[gb0 * 42 + gc0];
            gp1 = src[gb1 * 42 + gc1];
            if (v2) gp2 = src[gb2 * 42 + gc2];
        }
        if (tid < 192) {
            ulonglong2 acc[TB];
            #pragma unroll
            for (int r = 0; r < TB; ++r) {
                float4 g4 = gSd[(sg * TB + r) * 24 + jc];
                acc[r] = *reinterpret_cast<ulonglong2*>(&g4);
            }
            #pragma unroll
            for (int kk = 0; kk < KPAD; kk += 2) {
                ulonglong2 w0 = sWp[kk * NJC + jc];
                ulonglong2 w1 = sWp[(kk + 1) * NJC + jc];
                #pragma unroll
                for (int r = 0; r < TB; ++r) {
                    ulonglong2 a = *(const ulonglong2*)(arow + r * KP2 + kk);
                    acc[r].x = fma2_(a.x, w0.x, acc[r].x);
                    acc[r].y = fma2_(a.x, w0.y, acc[r].y);
                    acc[r].x = fma2_(a.y, w1.x, acc[r].x);
                    acc[r].y = fma2_(a.y, w1.y, acc[r].y);
                }
            }
            #pragma unroll
            for (int r = 0; r < TB; ++r)
                gSd[(sg * TB + r) * 24 + jc] = *reinterpret_cast<float4*>(&acc[r]);
        }
        __syncthreads();

        {
            float* orow = g_h2 + ((size_t)t * B_ + b0) * (2 * H2_) + dir * H;
            const float* gbase = gS + p * 32 * GP;
            int b = ab0, h = ah0;
            for (int e = tid; e < 32 * H; e += 256) {
                const float* grow = gbase + b * GP;
                float c = fsigm(grow[H + h]) * cS[e] + fsigm(grow[h]) * ftanh_(grow[2 * H + h]);
                cS[e] = c;
                float hn = fsigm(grow[3 * H + h]) * ftanh_(c);
                ((float2*)aS)[b * KP2 + h] = make_float2(hn, hn);
                orow[b * (2 * H2_) + h] = hn;
                b += 12; h += 4; if (h >= H) { h -= H; ++b; }
            }
        }
    }
}

// ================= dense head (smem-staged rows, padded pitch) =================
__global__ __launch_bounds__(256)
void dense_kernel(const float* __restrict__ wd1, const float* __restrict__ bd1,
                  const float* __restrict__ wd2, const float* __restrict__ bd2,
                  const float* __restrict__ wo,  const float* __restrict__ bo)
{
    constexpr int IN = 2 * H2_;   // 42
    constexpr int INP = 43;       // padded pitch (odd -> conflict-free)
    extern __shared__ float sm[];
    float* sIn = sm;                    // [256][43]
    float* s1  = sIn + 256 * INP;       // [30][42]
    float* sb1 = s1 + D1_ * IN;
    float* s2  = sb1 + D1_;             // [20][30]
    float* sb2 = s2 + D2_ * D1_;
    float* sWo = sb2 + D2_;
    float* sBo = sWo + D2_;

    const int tid = threadIdx.x;
    const size_t row0 = (size_t)blockIdx.x * 256;

    {
        const float* src = g_h2 + row0 * IN;
        int r = tid / IN, c = tid % IN;
        for (int q = tid; q < 256 * IN; q += 256) {
            sIn[r * INP + c] = src[q];
            r += 6; c += 4; if (c >= IN) { c -= IN; ++r; }
        }
    }
    for (int i = tid; i < D1_ * IN; i += 256) s1[i] = wd1[i];
    for (int i = tid; i < D2_ * D1_; i += 256) s2[i] = wd2[i];
    if (tid < D1_) sb1[tid] = bd1[tid];
    if (tid < D2_) { sb2[tid] = bd2[tid]; sWo[tid] = wo[tid]; }
    if (tid == 0) sBo[0] = bo[0];
    __syncthreads();

    const float* in = sIn + tid * INP;
    float acc2[D2_];
    #pragma unroll
    for (int k = 0; k < D2_; ++k) acc2[k] = sb2[k];
    #pragma unroll 2
    for (int j = 0; j < D1_; ++j) {
        float v = sb1[j];
        #pragma unroll
        for (int k = 0; k < IN; ++k) v = fmaf(in[k], s1[j * IN + k], v);
        v = fmaxf(v, 0.f);
        #pragma unroll
        for (int k = 0; k < D2_; ++k) acc2[k] = fmaf(v, s2[k * D1_ + j], acc2[k]);
    }
    float y = sBo[0];
    #pragma unroll
    for (int k = 0; k < D2_; ++k) y = fmaf(fmaxf(acc2[k], 0.f), sWo[k], y);

    g_y[row0 + tid] = y;   // t-major, coalesced
}

// ================= out transpose: g_y [T][B] -> out [B][T] =================
__global__ void transpose_out(float* __restrict__ out) {
    __shared__ float tile[32][33];
    const int b0 = blockIdx.x * 32, t0 = blockIdx.y * 32;
    const int tx = threadIdx.x, ty = threadIdx.y;
    for (int i = ty; i < 32; i += 8) {
        int t = t0 + i;
        if (t < T_) tile[i][tx] = g_y[(size_t)t * B_ + b0 + tx];
    }
    __syncthreads();
    for (int i = ty; i < 32; i += 8) {
        int t = t0 + tx;
        if (t < T_) out[(size_t)(b0 + i) * T_ + t] = tile[tx][i];
    }
}

// ---------------- host glue ----------------
extern "C" void kernel_launch(void* const* d_in, const int* in_sizes, int n_in,
                              void* d_out, int out_size)
{
    const float* x      = (const float*)d_in[0];
    const float* w1f_ih = (const float*)d_in[1];
    const float* w1f_hh = (const float*)d_in[2];
    const float* b1f_ih = (const float*)d_in[3];
    const float* b1f_hh = (const float*)d_in[4];
    const float* w1b_ih = (const float*)d_in[5];
    const float* w1b_hh = (const float*)d_in[6];
    const float* b1b_ih = (const float*)d_in[7];
    const float* b1b_hh = (const float*)d_in[8];
    const float* w2f_ih = (const float*)d_in[9];
    const float* w2f_hh = (const float*)d_in[10];
    const float* b2f_ih = (const float*)d_in[11];
    const float* b2f_hh = (const float*)d_in[12];
    const float* w2b_ih = (const float*)d_in[13];
    const float* w2b_hh = (const float*)d_in[14];
    const float* b2b_ih = (const float*)d_in[15];
    const float* b2b_hh = (const float*)d_in[16];
    const float* wd1    = (const float*)d_in[17];
    const float* bd1    = (const float*)d_in[18];
    const float* wd2    = (const float*)d_in[19];
    const float* bd2    = (const float*)d_in[20];
    const float* wo     = (const float*)d_in[21];
    const float* bo     = (const float*)d_in[22];
    float* out = (float*)d_out;

    const int SM1 = (80 * 288 + 32 * 288 + 32 * 82 * 2 + 32 * 70 + 288) * 4;  // 160128
    const int SMX = (140 * 168 + 96 * 142 * 2 + 168) * 4;                     // 203808
    const int SM2 = (24 * 96 + 2 * 32 * 96 + 32 * 24 * 2 + 32 * 21) * 4;      // 42624
    const int SMD = (256 * 43 + 30 * 42 + 30 + 20 * 30 + 20 + 20 + 1) * 4;    // ~51932

    cudaFuncSetAttribute(lstm1_kernel, cudaFuncAttributeMaxDynamicSharedMemorySize, SM1);
    cudaFuncSetAttribute(xg2_kernel,   cudaFuncAttributeMaxDynamicSharedMemorySize, SMX);
    cudaFuncSetAttribute(lstm2_kernel, cudaFuncAttributeMaxDynamicSharedMemorySize, SM2);
    cudaFuncSetAttribute(dense_kernel, cudaFuncAttributeMaxDynamicSharedMemorySize, SMD);

    transpose_x<<<(B_ * T_ * F_ + 255) / 256, 256>>>(x);
    prep_w2<<<(168 * 140 + 255) / 256, 256>>>(w2f_ih, w2b_ih, b2f_ih, b2f_hh, b2b_ih, b2b_hh);

    lstm1_kernel<<<dim3(B_ / 32, 2), 288, SM1>>>(
        w1f_ih, w1f_hh, b1f_ih, b1f_hh,
        w1b_ih, w1b_hh, b1b_ih, b1b_hh);

    xg2_kernel<<<(T_ * B_) / 96, 352, SMX>>>();

    lstm2_kernel<<<dim3(B_ / 32, 2), 256, SM2>>>(w2f_hh, w2b_hh);

    dense_kernel<<<(T_ * B_) / 256, 256, SMD>>>(wd1, bd1, wd2, bd2, wo, bo);

    transpose_out<<<dim3(B_ / 32, (T_ + 31) / 32), dim3(32, 8)>>>(out);
}

// round 6
// speedup vs baseline: 2.2692x; 1.1400x over previous
#include <cuda_runtime.h>
#include <cstdint>

#define B_  2048
#define T_  336
#define F_  10
#define H1_ 70
#define H2_ 21
#define D1_ 30
#define D2_ 20

typedef unsigned long long u64;

// ---------------- scratch (__device__ globals; no allocations) ----------------
__device__ float g_xT [(size_t)T_ * B_ * F_];          // x transposed [T][B][10]
__device__ float g_h1 [(size_t)T_ * B_ * (2*H1_)];     // layer1 out   [T][B][140]
__device__ float g_xg2[(size_t)T_ * B_ * (8*H2_)];     // layer2 input gates [T][B][168]
__device__ float g_h2 [(size_t)T_ * B_ * (2*H2_)];     // layer2 out   [T][B][42]
__device__ float g_y  [(size_t)T_ * B_];               // head out, t-major
__device__ float g_w2t[140 * 168];                     // W2_ih^T packed, both dirs
__device__ float g_b2 [168];

// ---------------- packed f32x2 fma ----------------
__device__ __forceinline__ u64 fma2_(u64 a, u64 b, u64 c) {
    u64 d;
    asm("fma.rn.f32x2 %0, %1, %2, %3;" : "=l"(d) : "l"(a), "l"(b), "l"(c));
    return d;
}

// ---------------- activations (accurate fast-math, ~1e-6 rel) ----------------
__device__ __forceinline__ float fsigm(float x) {
    return __fdividef(1.f, 1.f + __expf(-x));
}
__device__ __forceinline__ float ftanh_(float x) {
    return 1.f - 2.f * __fdividef(1.f, 1.f + __expf(2.f * x));
}

// ---------------- transpose x: [B][T][F] -> [T][B][F] ----------------
__global__ void transpose_x(const float* __restrict__ x) {
    int gid = blockIdx.x * blockDim.x + threadIdx.x;
    if (gid < B_ * T_ * F_) {
        int f = gid % F_;
        int t = (gid / F_) % T_;
        int b = gid / (F_ * T_);
        g_xT[((size_t)t * B_ + b) * F_ + f] = x[gid];
    }
}

// ---------------- prep: transpose layer-2 input weights to k-major ----------------
__global__ void prep_w2(const float* __restrict__ wf, const float* __restrict__ wb,
                        const float* __restrict__ bfi, const float* __restrict__ bfh,
                        const float* __restrict__ bbi, const float* __restrict__ bbh) {
    int i = blockIdx.x * blockDim.x + threadIdx.x;
    if (i < 168 * 140) {
        int jj = i / 140;
        int k  = i % 140;
        int dir = jj / 84, j = jj % 84;
        const float* w = dir ? wb : wf;
        g_w2t[k * 168 + jj] = w[j * 140 + k];
    }
    if (i < 168) {
        int dir = i / 84, j = i % 84;
        g_b2[i] = dir ? (bbi[j] + bbh[j]) : (bfi[j] + bfh[j]);
    }
}

// ================= layer 1: fused-input recurrent LSTM, K-split teams =================
// block = 32 samples x 1 direction; 576 threads = 2 K-teams x (4 SG x 72 chunks).
// Team ks sums k in [ks*40, ks*40+40) into partial gP[ks]; activation adds partials.
__global__ __launch_bounds__(576, 1)
void lstm1_kernel(const float* __restrict__ Wih_f, const float* __restrict__ Whh_f,
                  const float* __restrict__ bih_f, const float* __restrict__ bhh_f,
                  const float* __restrict__ Wih_b, const float* __restrict__ Whh_b,
                  const float* __restrict__ bih_b, const float* __restrict__ bhh_b)
{
    constexpr int I = 10, H = 70, K = 80, KP2 = 82, G = 280, GP = 288;
    constexpr int NJC = 72, TB = 8, NTH = 576, KH = 40;
    extern __shared__ float sm[];
    float* sW = sm;                    // [80][288] k-major
    float* gP = sW + K * GP;           // [2][32][288] partial gates
    float* aS = gP + 2 * 32 * GP;      // [32][82] duplicated pairs (float2)
    float* cS = aS + 32 * KP2 * 2;     // [32][70]
    float* sb = cS + 32 * H;           // [288]

    const int dir = blockIdx.y;
    const float* Wih = dir ? Wih_b : Wih_f;
    const float* Whh = dir ? Whh_b : Whh_f;
    const float* bih = dir ? bih_b : bih_f;
    const float* bhh = dir ? bhh_b : bhh_f;
    const int b0  = blockIdx.x * 32;
    const int tid = threadIdx.x;

    for (int idx = tid; idx < K * GP; idx += NTH) {
        int k = idx / GP, j = idx % GP;
        float v = 0.f;
        if (j < G) v = (k < I) ? Wih[j * I + k] : Whh[j * H + (k - I)];
        sW[idx] = v;
    }
    for (int j = tid; j < GP; j += NTH) sb[j] = (j < G) ? (bih[j] + bhh[j]) : 0.f;
    for (int idx = tid; idx < 32 * KP2 * 2; idx += NTH) aS[idx] = 0.f;
    for (int idx = tid; idx < 32 * H; idx += NTH) cS[idx] = 0.f;

    // x staging map: 320 x floats, tid<320 one each (stride-1 dup-pair stores)
    const bool xp = tid < 32 * I;
    const int xb0 = tid / I, xk0 = tid % I;
    // activation map start (element-consecutive; stride NTH=576 -> b+=8, h+=16)
    const int ab0 = tid / H, ah0 = tid % H;

    const int ks = tid / 288;           // K-team
    const int r288 = tid - ks * 288;
    const int sg = r288 / NJC, jc = r288 % NJC;
    const int kbase = ks * KH;
    const u64* arow = ((const u64*)aS) + (size_t)(sg * TB) * KP2;
    const ulonglong2* sWp = (const ulonglong2*)sW;
    ulonglong2* gPd = ((ulonglong2*)(gP + ks * 32 * GP));

    int t = dir ? (T_ - 1) : 0;
    const int tstep = dir ? -1 : 1;
    float xp0 = 0.f;
    if (xp) xp0 = g_xT[((size_t)t * B_ + b0) * I + tid];
    __syncthreads();

    for (int s = 0; s < T_; ++s, t += tstep) {
        // ---- stage x_t as duplicated pairs ----
        if (xp) ((float2*)aS)[xb0 * KP2 + xk0] = make_float2(xp0, xp0);
        __syncthreads();
        if (xp && s + 1 < T_)
            xp0 = g_xT[((size_t)(t + tstep) * B_ + b0) * I + tid];

        // ---- packed matvec partial: gP[ks] = (ks? 0 : bias) + a[krange] @ W[krange] ----
        {
            float4 b4 = make_float4(0.f, 0.f, 0.f, 0.f);
            if (ks == 0) b4 = ((const float4*)sb)[jc];
            ulonglong2 binit = *reinterpret_cast<ulonglong2*>(&b4);
            ulonglong2 acc[TB];
            #pragma unroll
            for (int r = 0; r < TB; ++r) acc[r] = binit;

            #pragma unroll 4
            for (int kk = 0; kk < KH; kk += 2) {
                const int k = kbase + kk;
                ulonglong2 w0 = sWp[k * NJC + jc];
                ulonglong2 w1 = sWp[(k + 1) * NJC + jc];
                #pragma unroll
                for (int r = 0; r < TB; ++r) {
                    ulonglong2 a = *(const ulonglong2*)(arow + r * KP2 + k);
                    acc[r].x = fma2_(a.x, w0.x, acc[r].x);
                    acc[r].y = fma2_(a.x, w0.y, acc[r].y);
                    acc[r].x = fma2_(a.y, w1.x, acc[r].x);
                    acc[r].y = fma2_(a.y, w1.y, acc[r].y);
                }
            }
            #pragma unroll
            for (int r = 0; r < TB; ++r) gPd[(sg * TB + r) * NJC + jc] = acc[r];
        }
        __syncthreads();

        // ---- gates: sum partials + state update + h store ----
        {
            float* orow = g_h1 + ((size_t)t * B_ + b0) * (2 * H1_) + dir * H;
            int b = ab0, h = ah0;
            for (int e = tid; e < 32 * H; e += NTH) {
                const float* g0 = gP + b * GP;
                const float* g1 = g0 + 32 * GP;
                float gi = g0[h]         + g1[h];
                float gf = g0[H + h]     + g1[H + h];
                float gg = g0[2 * H + h] + g1[2 * H + h];
                float go = g0[3 * H + h] + g1[3 * H + h];
                float c = fsigm(gf) * cS[e] + fsigm(gi) * ftanh_(gg);
                cS[e] = c;
                float hn = fsigm(go) * ftanh_(c);
                ((float2*)aS)[b * KP2 + I + h] = make_float2(hn, hn);
                orow[b * (2 * H1_) + h] = hn;
                b += 8; h += 16; if (h >= H) { h -= H; ++b; }
            }
        }
    }
}

// ================= layer-2 input GEMM: xg2 = h1 @ W2ih^T + biases =================
// block = 96 rows; K=140 (pairs, pitch 142), G=168; TB=12, NSG=8, NJC=42 -> 336 of 352 thr
__global__ __launch_bounds__(352, 1)
void xg2_kernel()
{
    constexpr int BB = 96, K = 140, KP2 = 142, G = 168, NJC = 42, TB = 12;
    extern __shared__ float sm[];
    float* sW = sm;                 // [140][168]
    float* aS = sW + K * G;         // [96][142] duplicated pairs
    float* sb = aS + BB * KP2 * 2;  // [168]
    const int tid = threadIdx.x;
    const size_t row0 = (size_t)blockIdx.x * BB;

    {
        const float4* wsrc = (const float4*)g_w2t;
        float4* wdst = (float4*)sW;
        for (int i = tid; i < K * G / 4; i += 352) wdst[i] = wsrc[i];
    }
    for (int j = tid; j < G; j += 352) sb[j] = g_b2[j];
    {
        const float* src = g_h1 + row0 * K;
        int r = tid / K, c = tid % K;
        for (int q = tid; q < BB * K; q += 352) {
            float v = src[q];
            ((float2*)aS)[r * KP2 + c] = make_float2(v, v);
            r += 2; c += 72; if (c >= K) { c -= K; ++r; }
        }
    }
    __syncthreads();

    if (tid < 336) {
        const int sg = tid / NJC, jc = tid % NJC;
        const u64* arow = ((const u64*)aS) + (size_t)(sg * TB) * KP2;
        const ulonglong2* sWp = (const ulonglong2*)sW;
        float4 b4 = ((const float4*)sb)[jc];
        ulonglong2 binit = *reinterpret_cast<ulonglong2*>(&b4);
        ulonglong2 acc[TB];
        #pragma unroll
        for (int r = 0; r < TB; ++r) acc[r] = binit;

        #pragma unroll 2
        for (int kk = 0; kk < K; kk += 2) {
            ulonglong2 w0 = sWp[kk * NJC + jc];
            ulonglong2 w1 = sWp[(kk + 1) * NJC + jc];
            #pragma unroll
            for (int r = 0; r < TB; ++r) {
                ulonglong2 a = *(const ulonglong2*)(arow + r * KP2 + kk);
                acc[r].x = fma2_(a.x, w0.x, acc[r].x);
                acc[r].y = fma2_(a.x, w0.y, acc[r].y);
                acc[r].x = fma2_(a.y, w1.x, acc[r].x);
                acc[r].y = fma2_(a.y, w1.y, acc[r].y);
            }
        }
        float4* outp = (float4*)(g_xg2 + row0 * G);
        #pragma unroll
        for (int r = 0; r < TB; ++r)
            outp[(sg * TB + r) * NJC + jc] = *reinterpret_cast<float4*>(&acc[r]);
    }
}

// ================= layer 2: recurrent-only LSTM (K=21 pad 24), K-split teams =================
// 384 threads = 2 K-teams x (8 SG x 24 chunks). Team0 seeds from input gates (gSd),
// team1 seeds zero into gP; activation adds gSd + gP.
__global__ __launch_bounds__(384, 1)
void lstm2_kernel(const float* __restrict__ Whh_f, const float* __restrict__ Whh_b)
{
    constexpr int H = 21, KPAD = 24, KP2 = 24, G = 84, GP = 96;
    constexpr int NJC = 24, TB = 4, NTH = 384, KH = 12;
    extern __shared__ float sm[];
    float* sW = sm;                 // [24][96]
    float* gS = sW + KPAD * GP;     // [2][32][96] input gates (double-buffered), team0 rmw
    float* gP = gS + 2 * 32 * GP;   // [32][96] team1 partial
    float* aS = gP + 32 * GP;       // [32][24] duplicated pairs
    float* cS = aS + 32 * KP2 * 2;  // [32][21]

    const int dir = blockIdx.y;
    const float* Whh = dir ? Whh_b : Whh_f;
    const int b0  = blockIdx.x * 32;
    const int tid = threadIdx.x;

    for (int idx = tid; idx < KPAD * GP; idx += NTH) {
        int k = idx / GP, j = idx % GP;
        sW[idx] = (k < H && j < G) ? Whh[j * H + k] : 0.f;
    }
    for (int idx = tid; idx < 32 * KP2 * 2; idx += NTH) aS[idx] = 0.f;
    for (int idx = tid; idx < 32 * H; idx += NTH) cS[idx] = 0.f;

    // g staging map (element-consecutive float4): slots tid, tid+384 of 672
    const int gb0 = tid / 21, gc0 = tid % 21;
    const int i1 = tid + NTH;
    const int gb1 = i1 / 21, gc1 = i1 % 21;
    const bool v1 = i1 < 672;
    // activation map start (stride NTH=384 -> b+=18, h+=6)
    const int ab0 = tid / H, ah0 = tid % H;

    const int ks = tid / 192;
    const int r192 = tid - ks * 192;
    const int sg = r192 / NJC, jc = r192 % NJC;
    const int kbase = ks * KH;
    const u64* arow = ((const u64*)aS) + (size_t)(sg * TB) * KP2;
    const ulonglong2* sWp = (const ulonglong2*)sW;

    int t = dir ? (T_ - 1) : 0;
    const int tstep = dir ? -1 : 1;
    float4 gp0, gp1;
    {
        const float4* src = (const float4*)(g_xg2 + ((size_t)t * B_ + b0) * 168 + dir * 84);
        gp0 = src[gb0 * 42 + gc0];
        if (v1) gp1 = src[gb1 * 42 + gc1];
    }
    __syncthreads();

    for (int s = 0; s < T_; ++s, t += tstep) {
        const int p = s & 1;
        float* gSb = gS + p * 32 * GP;
        float4* gSd = (float4*)gSb;
        gSd[gb0 * 24 + gc0] = gp0;
        if (v1) gSd[gb1 * 24 + gc1] = gp1;
        __syncthreads();
        if (s + 1 < T_) {
            const float4* src = (const float4*)(g_xg2 + ((size_t)(t + tstep) * B_ + b0) * 168 + dir * 84);
            gp0 = src[gb0 * 42 + gc0];
            if (v1) gp1 = src[gb1 * 42 + gc1];
        }
        // ---- matvec partial ----
        {
            ulonglong2* dst = (ulonglong2*)(ks ? gP : gSb);
            ulonglong2 acc[TB];
            #pragma unroll
            for (int r = 0; r < TB; ++r) {
                if (ks == 0) acc[r] = ((const ulonglong2*)gSb)[(sg * TB + r) * NJC + jc];
                else         acc[r] = make_ulonglong2(0ull, 0ull);
            }
            #pragma unroll
            for (int kk = 0; kk < KH; kk += 2) {
                const int k = kbase + kk;
                ulonglong2 w0 = sWp[k * NJC + jc];
                ulonglong2 w1 = sWp[(k + 1) * NJC + jc];
                #pragma unroll
                for (int r = 0; r < TB; ++r) {
                    ulonglong2 a = *(const ulonglong2*)(arow + r * KP2 + k);
                    acc[r].x = fma2_(a.x, w0.x, acc[r].x);
                    acc[r].y = fma2_(a.x, w0.y, acc[r].y);
                    acc[r].x = fma2_(a.y, w1.x, acc[r].x);
                    acc[r].y = fma2_(a.y, w1.y, acc[r].y);
                }
            }
            #pragma unroll
            for (int r = 0; r < TB; ++r)
                dst[(sg * TB + r) * NJC + jc] = acc[r];
        }
        __syncthreads();

        // ---- gates: gSd + gP partial sum, state update, h store ----
        {
            float* orow = g_h2 + ((size_t)t * B_ + b0) * (2 * H2_) + dir * H;
            int b = ab0, h = ah0;
            for (int e = tid; e < 32 * H; e += NTH) {
                const float* g0 = gSb + b * GP;
                const float* g1 = gP + b * GP;
                float gi = g0[h]         + g1[h];
                float gf = g0[H + h]     + g1[H + h];
                float gg = g0[2 * H + h] + g1[2 * H + h];
                float go = g0[3 * H + h] + g1[3 * H + h];
                float c = fsigm(gf) * cS[e] + fsigm(gi) * ftanh_(gg);
                cS[e] = c;
                float hn = fsigm(go) * ftanh_(c);
                ((float2*)aS)[b * KP2 + h] = make_float2(hn, hn);
                orow[b * (2 * H2_) + h] = hn;
                b += 18; h += 6; if (h >= H) { h -= H; ++b; }
            }
        }
    }
}

// ================= dense head (smem-staged rows, padded pitch) =================
__global__ __launch_bounds__(256)
void dense_kernel(const float* __restrict__ wd1, const float* __restrict__ bd1,
                  const float* __restrict__ wd2, const float* __restrict__ bd2,
                  const float* __restrict__ wo,  const float* __restrict__ bo)
{
    constexpr int IN = 2 * H2_;   // 42
    constexpr int INP = 43;       // padded pitch (odd -> conflict-free)
    extern __shared__ float sm[];
    float* sIn = sm;                    // [256][43]
    float* s1  = sIn + 256 * INP;       // [30][42]
    float* sb1 = s1 + D1_ * IN;
    float* s2  = sb1 + D1_;             // [20][30]
    float* sb2 = s2 + D2_ * D1_;
    float* sWo = sb2 + D2_;
    float* sBo = sWo + D2_;

    const int tid = threadIdx.x;
    const size_t row0 = (size_t)blockIdx.x * 256;

    {
        const float* src = g_h2 + row0 * IN;
        int r = tid / IN, c = tid % IN;
        for (int q = tid; q < 256 * IN; q += 256) {
            sIn[r * INP + c] = src[q];
            r += 6; c += 4; if (c >= IN) { c -= IN; ++r; }
        }
    }
    for (int i = tid; i < D1_ * IN; i += 256) s1[i] = wd1[i];
    for (int i = tid; i < D2_ * D1_; i += 256) s2[i] = wd2[i];
    if (tid < D1_) sb1[tid] = bd1[tid];
    if (tid < D2_) { sb2[tid] = bd2[tid]; sWo[tid] = wo[tid]; }
    if (tid == 0) sBo[0] = bo[0];
    __syncthreads();

    const float* in = sIn + tid * INP;
    float acc2[D2_];
    #pragma unroll
    for (int k = 0; k < D2_; ++k) acc2[k] = sb2[k];
    #pragma unroll 2
    for (int j = 0; j < D1_; ++j) {
        float v = sb1[j];
        #pragma unroll
        for (int k = 0; k < IN; ++k) v = fmaf(in[k], s1[j * IN + k], v);
        v = fmaxf(v, 0.f);
        #pragma unroll
        for (int k = 0; k < D2_; ++k) acc2[k] = fmaf(v, s2[k * D1_ + j], acc2[k]);
    }
    float y = sBo[0];
    #pragma unroll
    for (int k = 0; k < D2_; ++k) y = fmaf(fmaxf(acc2[k], 0.f), sWo[k], y);

    g_y[row0 + tid] = y;   // t-major, coalesced
}

// ================= out transpose: g_y [T][B] -> out [B][T] =================
__global__ void transpose_out(float* __restrict__ out) {
    __shared__ float tile[32][33];
    const int b0 = blockIdx.x * 32, t0 = blockIdx.y * 32;
    const int tx = threadIdx.x, ty = threadIdx.y;
    for (int i = ty; i < 32; i += 8) {
        int t = t0 + i;
        if (t < T_) tile[i][tx] = g_y[(size_t)t * B_ + b0 + tx];
    }
    __syncthreads();
    for (int i = ty; i < 32; i += 8) {
        int t = t0 + tx;
        if (t < T_) out[(size_t)(b0 + i) * T_ + t] = tile[tx][i];
    }
}

// ---------------- host glue ----------------
extern "C" void kernel_launch(void* const* d_in, const int* in_sizes, int n_in,
                              void* d_out, int out_size)
{
    const float* x      = (const float*)d_in[0];
    const float* w1f_ih = (const float*)d_in[1];
    const float* w1f_hh = (const float*)d_in[2];
    const float* b1f_ih = (const float*)d_in[3];
    const float* b1f_hh = (const float*)d_in[4];
    const float* w1b_ih = (const float*)d_in[5];
    const float* w1b_hh = (const float*)d_in[6];
    const float* b1b_ih = (const float*)d_in[7];
    const float* b1b_hh = (const float*)d_in[8];
    const float* w2f_ih = (const float*)d_in[9];
    const float* w2f_hh = (const float*)d_in[10];
    const float* b2f_ih = (const float*)d_in[11];
    const float* b2f_hh = (const float*)d_in[12];
    const float* w2b_ih = (const float*)d_in[13];
    const float* w2b_hh = (const float*)d_in[14];
    const float* b2b_ih = (const float*)d_in[15];
    const float* b2b_hh = (const float*)d_in[16];
    const float* wd1    = (const float*)d_in[17];
    const float* bd1    = (const float*)d_in[18];
    const float* wd2    = (const float*)d_in[19];
    const float* bd2    = (const float*)d_in[20];
    const float* wo     = (const float*)d_in[21];
    const float* bo     = (const float*)d_in[22];
    float* out = (float*)d_out;

    const int SM1 = (80 * 288 + 2 * 32 * 288 + 32 * 82 * 2 + 32 * 70 + 288) * 4;        // 196992
    const int SMX = (140 * 168 + 96 * 142 * 2 + 168) * 4;                               // 203808
    const int SM2 = (24 * 96 + 2 * 32 * 96 + 32 * 96 + 32 * 24 * 2 + 32 * 21) * 4;      // 54912
    const int SMD = (256 * 43 + 30 * 42 + 30 + 20 * 30 + 20 + 20 + 1) * 4;              // ~51932

    cudaFuncSetAttribute(lstm1_kernel, cudaFuncAttributeMaxDynamicSharedMemorySize, SM1);
    cudaFuncSetAttribute(xg2_kernel,   cudaFuncAttributeMaxDynamicSharedMemorySize, SMX);
    cudaFuncSetAttribute(lstm2_kernel, cudaFuncAttributeMaxDynamicSharedMemorySize, SM2);
    cudaFuncSetAttribute(dense_kernel, cudaFuncAttributeMaxDynamicSharedMemorySize, SMD);

    transpose_x<<<(B_ * T_ * F_ + 255) / 256, 256>>>(x);
    prep_w2<<<(168 * 140 + 255) / 256, 256>>>(w2f_ih, w2b_ih, b2f_ih, b2f_hh, b2b_ih, b2b_hh);

    lstm1_kernel<<<dim3(B_ / 32, 2), 576, SM1>>>(
        w1f_ih, w1f_hh, b1f_ih, b1f_hh,
        w1b_ih, w1b_hh, b1b_ih, b1b_hh);

    xg2_kernel<<<(T_ * B_) / 96, 352, SMX>>>();

    lstm2_kernel<<<dim3(B_ / 32, 2), 384, SM2>>>(w2f_hh, w2b_hh);

    dense_kernel<<<(T_ * B_) / 256, 256, SMD>>>(wd1, bd1, wd2, bd2, wo, bo);

    transpose_out<<<dim3(B_ / 32, (T_ + 31) / 32), dim3(32, 8)>>>(out);
}